// round 1
// baseline (speedup 1.0000x reference)
#include <cuda_runtime.h>
#include <math.h>

#define BATCH 32
#define HH 56
#define WW 56
#define CC 192
#define NHEAD 6
#define HDIM 32
#define NTOK 49
#define HIDDEN 768
#define TOKENS (BATCH*HH*WW)

// Scratch (device globals — no runtime allocation allowed)
__device__ float g_buf0[TOKENS*CC];  // shortcut (after cpe0)
__device__ float g_buf1[TOKENS*CC];  // y (after attn residual)
__device__ float g_buf2[TOKENS*CC];  // y2 (after cpe1)

__device__ __forceinline__ float gelu_exact(float x) {
    return 0.5f * x * (1.f + erff(x * 0.7071067811865475f));
}

// ---------------------------------------------------------------------------
// Depthwise 3x3 conv (SAME) + residual:  out = in + conv(in) + bias
// One block per (h, b) row; 192 threads = channels. Sliding 3-column window
// in registers: 3 new loads per output instead of 9.
// ---------------------------------------------------------------------------
__global__ void cpe_kernel(const float* __restrict__ in,
                           const float* __restrict__ wgt,
                           const float* __restrict__ bias,
                           float* __restrict__ out)
{
    int h = blockIdx.x;
    int b = blockIdx.y;
    int c = threadIdx.x;
    float kw[9];
#pragma unroll
    for (int i = 0; i < 9; i++) kw[i] = wgt[c*9 + i];
    float bb = bias[c];
    const float* base  = in  + ((size_t)b*HH*WW)*CC + c;
    float*       obase = out + ((size_t)b*HH*WW)*CC + c;

    float colL[3], colM[3], colR[3];
#pragma unroll
    for (int dy = 0; dy < 3; dy++) {
        colL[dy] = 0.f;
        int hy = h + dy - 1;
        colM[dy] = (hy >= 0 && hy < HH) ? base[(size_t)(hy*WW)*CC] : 0.f;
    }
    for (int x = 0; x < WW; x++) {
#pragma unroll
        for (int dy = 0; dy < 3; dy++) {
            int hy = h + dy - 1;
            colR[dy] = (x+1 < WW && hy >= 0 && hy < HH)
                       ? base[(size_t)(hy*WW + x + 1)*CC] : 0.f;
        }
        float acc = bb;
#pragma unroll
        for (int dy = 0; dy < 3; dy++) {
            acc = fmaf(kw[dy*3+0], colL[dy], acc);
            acc = fmaf(kw[dy*3+1], colM[dy], acc);
            acc = fmaf(kw[dy*3+2], colR[dy], acc);
        }
        obase[(size_t)(h*WW + x)*CC] = colM[1] + acc;
#pragma unroll
        for (int dy = 0; dy < 3; dy++) { colL[dy] = colM[dy]; colM[dy] = colR[dy]; }
    }
}

// ---------------------------------------------------------------------------
// Fused LN1 + window attention + proj + residual.
// One block per window. Window (b, i, j): token n -> pixel
//   h = (n/7)*8 + i, w = (n%7)*8 + j   (faithful to the 'b (w_h nw_h)...' split)
// qkv column layout (faithful to reshape (d,3,h)): q: d*18+h, k: d*18+6+h, v: d*18+12+h
// ---------------------------------------------------------------------------
#define ATTN_SMEM_FLOATS (64*192 + 49*576 + 192*64 + 49*52)
#define ATTN_SMEM_BYTES  (ATTN_SMEM_FLOATS*4)

__global__ __launch_bounds__(256) void attn_kernel(
    const float* __restrict__ sc,
    const float* __restrict__ n1g, const float* __restrict__ n1b,
    const float* __restrict__ qkvw, const float* __restrict__ qkvb,
    const float* __restrict__ projw, const float* __restrict__ projb,
    float* __restrict__ yout)
{
    extern __shared__ float sm[];
    float* s_x   = sm;                   // [64][192] LN'd tokens, later attn output o
    float* s_qkv = s_x + 64*192;         // [49][576]
    float* s_w   = s_qkv + 49*576;       // [192][64] weight tile / [32][49] kT
    float* s_p   = s_w + 192*64;         // [49][52] scores/probs

    int widx = blockIdx.x;
    int b  = widx >> 6;
    int wi = (widx >> 3) & 7;
    int wj = widx & 7;
    int tid  = threadIdx.x;
    int warp = tid >> 5, lane = tid & 31;

    // ---- load 49 tokens (rows 49..63 zero-padded) ----
    for (int idx = tid; idx < 64*CC; idx += 256) {
        int n = idx / CC, c = idx % CC;
        float v = 0.f;
        if (n < NTOK) {
            int h  = (n/7)*8 + wi;
            int w2 = (n%7)*8 + wj;
            v = sc[(((size_t)b*HH + h)*WW + w2)*CC + c];
        }
        s_x[idx] = v;
    }
    __syncthreads();

    // ---- LayerNorm per token ----
    for (int n = warp; n < NTOK; n += 8) {
        float vals[6]; float s = 0.f;
#pragma unroll
        for (int u = 0; u < 6; u++) { vals[u] = s_x[n*CC + lane + u*32]; s += vals[u]; }
#pragma unroll
        for (int o = 16; o; o >>= 1) s += __shfl_xor_sync(0xffffffffu, s, o);
        float m = s * (1.f/192.f);
        float vv = 0.f;
#pragma unroll
        for (int u = 0; u < 6; u++) { float d = vals[u]-m; vv += d*d; }
#pragma unroll
        for (int o = 16; o; o >>= 1) vv += __shfl_xor_sync(0xffffffffu, vv, o);
        float rs = rsqrtf(vv*(1.f/192.f) + 1e-5f);
#pragma unroll
        for (int u = 0; u < 6; u++) {
            int c = lane + u*32;
            s_x[n*CC + c] = (vals[u]-m)*rs*n1g[c] + n1b[c];
        }
    }
    __syncthreads();

    int tc = tid & 15, tr = tid >> 4;
    int j0 = tc*4;

    // ---- qkv GEMM: [49,192] x [192,576] ----
    for (int jt = 0; jt < 9; jt++) {
        for (int i = tid; i < 192*64; i += 256) {
            int k = i >> 6, j = i & 63;
            s_w[i] = qkvw[k*576 + jt*64 + j];
        }
        __syncthreads();
        float acc[4][4];
#pragma unroll
        for (int g = 0; g < 4; g++) {
            float bv = qkvb[jt*64 + j0 + g];
#pragma unroll
            for (int m = 0; m < 4; m++) acc[m][g] = bv;
        }
#pragma unroll 4
        for (int k = 0; k < CC; k++) {
            float4 bv = *(const float4*)&s_w[k*64 + j0];
#pragma unroll
            for (int m = 0; m < 4; m++) {
                float a = s_x[(tr + 16*m)*CC + k];
                acc[m][0] = fmaf(a, bv.x, acc[m][0]);
                acc[m][1] = fmaf(a, bv.y, acc[m][1]);
                acc[m][2] = fmaf(a, bv.z, acc[m][2]);
                acc[m][3] = fmaf(a, bv.w, acc[m][3]);
            }
        }
#pragma unroll
        for (int m = 0; m < 4; m++) {
            int n = tr + 16*m;
            if (n < NTOK) {
                *(float4*)&s_qkv[n*576 + jt*64 + j0] =
                    make_float4(acc[m][0], acc[m][1], acc[m][2], acc[m][3]);
            }
        }
        __syncthreads();
    }

    // ---- attention, head by head ----
    const float scale = 0.17677669529663687f;  // 32^-0.5
    float* s_kt = s_w;                          // [32][49] transposed K
    for (int hh2 = 0; hh2 < NHEAD; hh2++) {
        // transpose K for conflict-free score GEMM (stride 49 is odd)
        for (int idx = tid; idx < NTOK*HDIM; idx += 256) {
            int j2 = idx >> 5, d = idx & 31;
            s_kt[d*NTOK + j2] = s_qkv[j2*576 + 6 + hh2 + d*18];
        }
        __syncthreads();
        // scores
        for (int idx = tid; idx < NTOK*NTOK; idx += 256) {
            int i2 = idx / NTOK, j2 = idx % NTOK;
            const float* q = &s_qkv[i2*576 + hh2];
            float s = 0.f;
#pragma unroll
            for (int d = 0; d < HDIM; d++)
                s = fmaf(q[d*18], s_kt[d*NTOK + j2], s);
            s_p[i2*52 + j2] = s * scale;
        }
        __syncthreads();
        // softmax rows
        for (int i2 = warp; i2 < NTOK; i2 += 8) {
            float v1 = s_p[i2*52 + lane];
            bool has2 = (lane + 32) < NTOK;
            float v2 = has2 ? s_p[i2*52 + lane + 32] : -INFINITY;
            float mx = fmaxf(v1, v2);
#pragma unroll
            for (int o = 16; o; o >>= 1) mx = fmaxf(mx, __shfl_xor_sync(0xffffffffu, mx, o));
            float e1 = expf(v1 - mx);
            float e2 = has2 ? expf(v2 - mx) : 0.f;
            float ss = e1 + e2;
#pragma unroll
            for (int o = 16; o; o >>= 1) ss += __shfl_xor_sync(0xffffffffu, ss, o);
            float inv = 1.f / ss;
            s_p[i2*52 + lane] = e1 * inv;
            if (has2) s_p[i2*52 + lane + 32] = e2 * inv;
        }
        __syncthreads();
        // out = P @ V  -> s_x[n][h*32+d]
        for (int idx = tid; idx < NTOK*HDIM; idx += 256) {
            int i2 = idx >> 5, d = idx & 31;
            const float* vv = &s_qkv[d*18 + 12 + hh2];
            const float* pp = &s_p[i2*52];
            float s = 0.f;
#pragma unroll
            for (int j2 = 0; j2 < NTOK; j2++)
                s = fmaf(pp[j2], vv[j2*576], s);
            s_x[i2*CC + hh2*HDIM + d] = s;
        }
        __syncthreads();
    }

    // ---- proj GEMM [49,192]x[192,192] + residual, scatter to global ----
    for (int jt = 0; jt < 3; jt++) {
        for (int i = tid; i < 192*64; i += 256) {
            int k = i >> 6, j = i & 63;
            s_w[i] = projw[k*CC + jt*64 + j];
        }
        __syncthreads();
        float acc[4][4];
#pragma unroll
        for (int g = 0; g < 4; g++) {
            float bv = projb[jt*64 + j0 + g];
#pragma unroll
            for (int m = 0; m < 4; m++) acc[m][g] = bv;
        }
#pragma unroll 4
        for (int k = 0; k < CC; k++) {
            float4 bv = *(const float4*)&s_w[k*64 + j0];
#pragma unroll
            for (int m = 0; m < 4; m++) {
                float a = s_x[(tr + 16*m)*CC + k];
                acc[m][0] = fmaf(a, bv.x, acc[m][0]);
                acc[m][1] = fmaf(a, bv.y, acc[m][1]);
                acc[m][2] = fmaf(a, bv.z, acc[m][2]);
                acc[m][3] = fmaf(a, bv.w, acc[m][3]);
            }
        }
#pragma unroll
        for (int m = 0; m < 4; m++) {
            int n = tr + 16*m;
            if (n < NTOK) {
                int h  = (n/7)*8 + wi;
                int w2 = (n%7)*8 + wj;
                size_t gbase = (((size_t)b*HH + h)*WW + w2)*CC + jt*64 + j0;
#pragma unroll
                for (int g = 0; g < 4; g++)
                    yout[gbase + g] = sc[gbase + g] + acc[m][g];
            }
        }
        __syncthreads();
    }
}

// ---------------------------------------------------------------------------
// Fused LN2 + MLP (fc1 -> gelu -> fc2) + residual. 64 tokens per block.
// fc2 accumulators persist in registers across the 12 hidden tiles.
// ---------------------------------------------------------------------------
#define MLP_SMEM_FLOATS (64*192 + 64*64 + 192*64)
#define MLP_SMEM_BYTES  (MLP_SMEM_FLOATS*4)

__global__ __launch_bounds__(256) void mlp_kernel(
    const float* __restrict__ y2,
    const float* __restrict__ n2g, const float* __restrict__ n2b,
    const float* __restrict__ fc1w, const float* __restrict__ fc1b,
    const float* __restrict__ fc2w, const float* __restrict__ fc2b,
    float* __restrict__ out)
{
    extern __shared__ float sm[];
    float* s_x = sm;            // [64][192]
    float* s_h = s_x + 64*192;  // [64][64]
    float* s_w = s_h + 64*64;   // [192][64] fc1 tile / [64][192] fc2 tile

    int tid = threadIdx.x;
    size_t t0 = (size_t)blockIdx.x * 64;

    for (int i = tid; i < 64*CC; i += 256) s_x[i] = y2[t0*CC + i];
    __syncthreads();

    int warp = tid >> 5, lane = tid & 31;
    for (int n = warp; n < 64; n += 8) {
        float vals[6]; float s = 0.f;
#pragma unroll
        for (int u = 0; u < 6; u++) { vals[u] = s_x[n*CC + lane + u*32]; s += vals[u]; }
#pragma unroll
        for (int o = 16; o; o >>= 1) s += __shfl_xor_sync(0xffffffffu, s, o);
        float m = s * (1.f/192.f);
        float vv = 0.f;
#pragma unroll
        for (int u = 0; u < 6; u++) { float d = vals[u]-m; vv += d*d; }
#pragma unroll
        for (int o = 16; o; o >>= 1) vv += __shfl_xor_sync(0xffffffffu, vv, o);
        float rs = rsqrtf(vv*(1.f/192.f) + 1e-5f);
#pragma unroll
        for (int u = 0; u < 6; u++) {
            int c = lane + u*32;
            s_x[n*CC + c] = (vals[u]-m)*rs*n2g[c] + n2b[c];
        }
    }
    __syncthreads();

    int tc = tid & 15, tr = tid >> 4;
    float acc[4][12];
#pragma unroll
    for (int r = 0; r < 4; r++)
#pragma unroll
        for (int g = 0; g < 12; g++) acc[r][g] = 0.f;

    for (int ht = 0; ht < 12; ht++) {
        // fc1 weight tile [192][64]
        for (int i = tid; i < 192*64; i += 256) {
            int k = i >> 6, j = i & 63;
            s_w[i] = fc1w[k*HIDDEN + ht*64 + j];
        }
        __syncthreads();
        float hacc[4][4];
#pragma unroll
        for (int g = 0; g < 4; g++) {
            float bv = fc1b[ht*64 + tc*4 + g];
#pragma unroll
            for (int r = 0; r < 4; r++) hacc[r][g] = bv;
        }
#pragma unroll 4
        for (int k = 0; k < CC; k++) {
            float4 bv = *(const float4*)&s_w[k*64 + tc*4];
#pragma unroll
            for (int r = 0; r < 4; r++) {
                float a = s_x[(tr*4 + r)*CC + k];
                hacc[r][0] = fmaf(a, bv.x, hacc[r][0]);
                hacc[r][1] = fmaf(a, bv.y, hacc[r][1]);
                hacc[r][2] = fmaf(a, bv.z, hacc[r][2]);
                hacc[r][3] = fmaf(a, bv.w, hacc[r][3]);
            }
        }
#pragma unroll
        for (int r = 0; r < 4; r++) {
            float4 o4;
            o4.x = gelu_exact(hacc[r][0]);
            o4.y = gelu_exact(hacc[r][1]);
            o4.z = gelu_exact(hacc[r][2]);
            o4.w = gelu_exact(hacc[r][3]);
            *(float4*)&s_h[(tr*4 + r)*64 + tc*4] = o4;
        }
        __syncthreads();
        // fc2 weight tile [64][192]
        for (int i = tid; i < 64*CC; i += 256) {
            int k = i / CC, c = i % CC;
            s_w[i] = fc2w[(ht*64 + k)*CC + c];
        }
        __syncthreads();
#pragma unroll 2
        for (int k = 0; k < 64; k++) {
            float a[4];
#pragma unroll
            for (int r = 0; r < 4; r++) a[r] = s_h[(tr*4 + r)*64 + k];
#pragma unroll
            for (int g3 = 0; g3 < 3; g3++) {
                float4 bv = *(const float4*)&s_w[k*CC + g3*64 + tc*4];
#pragma unroll
                for (int r = 0; r < 4; r++) {
                    acc[r][g3*4+0] = fmaf(a[r], bv.x, acc[r][g3*4+0]);
                    acc[r][g3*4+1] = fmaf(a[r], bv.y, acc[r][g3*4+1]);
                    acc[r][g3*4+2] = fmaf(a[r], bv.z, acc[r][g3*4+2]);
                    acc[r][g3*4+3] = fmaf(a[r], bv.w, acc[r][g3*4+3]);
                }
            }
        }
        __syncthreads();
    }

#pragma unroll
    for (int r = 0; r < 4; r++) {
        size_t row = t0 + tr*4 + r;
#pragma unroll
        for (int g3 = 0; g3 < 3; g3++) {
#pragma unroll
            for (int g = 0; g < 4; g++) {
                int col = g3*64 + tc*4 + g;
                out[row*CC + col] = y2[row*CC + col] + fc2b[col] + acc[r][g3*4 + g];
            }
        }
    }
}

// ---------------------------------------------------------------------------
extern "C" void kernel_launch(void* const* d_in, const int* in_sizes, int n_in,
                              void* d_out, int out_size)
{
    // Input order: x, [H, W scalars], cpe0_w, cpe0_b, cpe1_w, cpe1_b, n1_g, n1_b,
    // qkv_w, qkv_b, proj_w, proj_b, n2_g, n2_b, fc1_w, fc1_b, fc2_w, fc2_b
    int p = 0;
    const float* x = (const float*)d_in[p++];
    while (p < n_in && in_sizes[p] == 1) p++;   // skip scalar H, W if present
    const float* cpe0_w = (const float*)d_in[p++];
    const float* cpe0_b = (const float*)d_in[p++];
    const float* cpe1_w = (const float*)d_in[p++];
    const float* cpe1_b = (const float*)d_in[p++];
    const float* n1_g   = (const float*)d_in[p++];
    const float* n1_b   = (const float*)d_in[p++];
    const float* qkv_w  = (const float*)d_in[p++];
    const float* qkv_b  = (const float*)d_in[p++];
    const float* proj_w = (const float*)d_in[p++];
    const float* proj_b = (const float*)d_in[p++];
    const float* n2_g   = (const float*)d_in[p++];
    const float* n2_b   = (const float*)d_in[p++];
    const float* fc1_w  = (const float*)d_in[p++];
    const float* fc1_b  = (const float*)d_in[p++];
    const float* fc2_w  = (const float*)d_in[p++];
    const float* fc2_b  = (const float*)d_in[p++];

    float *b0, *b1, *b2;
    cudaGetSymbolAddress((void**)&b0, g_buf0);
    cudaGetSymbolAddress((void**)&b1, g_buf1);
    cudaGetSymbolAddress((void**)&b2, g_buf2);

    cudaFuncSetAttribute(attn_kernel, cudaFuncAttributeMaxDynamicSharedMemorySize,
                         ATTN_SMEM_BYTES);
    cudaFuncSetAttribute(mlp_kernel, cudaFuncAttributeMaxDynamicSharedMemorySize,
                         MLP_SMEM_BYTES);

    dim3 gcpe(HH, BATCH);
    cpe_kernel<<<gcpe, CC>>>(x, cpe0_w, cpe0_b, b0);
    attn_kernel<<<BATCH*64, 256, ATTN_SMEM_BYTES>>>(b0, n1_g, n1_b, qkv_w, qkv_b,
                                                    proj_w, proj_b, b1);
    cpe_kernel<<<gcpe, CC>>>(b1, cpe1_w, cpe1_b, b2);
    mlp_kernel<<<TOKENS/64, 256, MLP_SMEM_BYTES>>>(b2, n2_g, n2_b, fc1_w, fc1_b,
                                                   fc2_w, fc2_b, (float*)d_out);
}

// round 2
// speedup vs baseline: 1.7559x; 1.7559x over previous
#include <cuda_runtime.h>
#include <math.h>

#define BATCH 32
#define HH 56
#define WW 56
#define CC 192
#define NHEAD 6
#define HDIM 32
#define NTOK 49
#define HIDDEN 768
#define TOKENS (BATCH*HH*WW)

// Scratch (device globals — no runtime allocation allowed)
__device__ float g_buf0[TOKENS*CC];  // shortcut (after cpe0)
__device__ float g_buf1[TOKENS*CC];  // y (after attn residual)
__device__ float g_buf2[TOKENS*CC];  // y2 (after cpe1)

__device__ __forceinline__ float gelu_exact(float x) {
    return 0.5f * x * (1.f + erff(x * 0.7071067811865475f));
}

// Packed dual-fp32 FMA: d.x += a.x*b.x ; d.y += a.y*b.y  (one instruction)
__device__ __forceinline__ void ffma2(float2& d, float2 a, float2 b) {
    asm("fma.rn.f32x2 %0, %1, %2, %0;"
        : "+l"(reinterpret_cast<unsigned long long&>(d))
        : "l"(reinterpret_cast<unsigned long long&>(a)),
          "l"(reinterpret_cast<unsigned long long&>(b)));
}

// ---------------------------------------------------------------------------
// Depthwise 3x3 conv (SAME) + residual:  out = in + conv(in) + bias
// ---------------------------------------------------------------------------
__global__ void cpe_kernel(const float* __restrict__ in,
                           const float* __restrict__ wgt,
                           const float* __restrict__ bias,
                           float* __restrict__ out)
{
    int h = blockIdx.x;
    int b = blockIdx.y;
    int c = threadIdx.x;
    float kw[9];
#pragma unroll
    for (int i = 0; i < 9; i++) kw[i] = wgt[c*9 + i];
    float bb = bias[c];
    const float* base  = in  + ((size_t)b*HH*WW)*CC + c;
    float*       obase = out + ((size_t)b*HH*WW)*CC + c;

    float colL[3], colM[3], colR[3];
#pragma unroll
    for (int dy = 0; dy < 3; dy++) {
        colL[dy] = 0.f;
        int hy = h + dy - 1;
        colM[dy] = (hy >= 0 && hy < HH) ? base[(size_t)(hy*WW)*CC] : 0.f;
    }
    for (int x = 0; x < WW; x++) {
#pragma unroll
        for (int dy = 0; dy < 3; dy++) {
            int hy = h + dy - 1;
            colR[dy] = (x+1 < WW && hy >= 0 && hy < HH)
                       ? base[(size_t)(hy*WW + x + 1)*CC] : 0.f;
        }
        float acc = bb;
#pragma unroll
        for (int dy = 0; dy < 3; dy++) {
            acc = fmaf(kw[dy*3+0], colL[dy], acc);
            acc = fmaf(kw[dy*3+1], colM[dy], acc);
            acc = fmaf(kw[dy*3+2], colR[dy], acc);
        }
        obase[(size_t)(h*WW + x)*CC] = colM[1] + acc;
#pragma unroll
        for (int dy = 0; dy < 3; dy++) { colL[dy] = colM[dy]; colM[dy] = colR[dy]; }
    }
}

// ---------------------------------------------------------------------------
// Fused LN1 + window attention + proj + residual.  512 threads/block.
// Window (b, i, j): token n -> pixel h=(n/7)*8+i, w=(n%7)*8+j
// qkv column (faithful (d,3,h) split): q: d*18+h, k: d*18+6+h, v: d*18+12+h
// ---------------------------------------------------------------------------
#define ATTN_SMEM_FLOATS (64*192 + 49*576 + 192*64 + 2*49*52)
#define ATTN_SMEM_BYTES  (ATTN_SMEM_FLOATS*4)

__global__ __launch_bounds__(512) void attn_kernel(
    const float* __restrict__ sc,
    const float* __restrict__ n1g, const float* __restrict__ n1b,
    const float* __restrict__ qkvw, const float* __restrict__ qkvb,
    const float* __restrict__ projw, const float* __restrict__ projb,
    float* __restrict__ yout)
{
    extern __shared__ float sm[];
    float* s_x   = sm;                   // [64][192] LN'd tokens, later attn out
    float* s_qkv = s_x + 64*192;         // [49][576]
    float* s_w   = s_qkv + 49*576;       // [192][64] weight tile / [2][32][50] kT
    float* s_p   = s_w + 192*64;         // [2][49][52] scores/probs

    int widx = blockIdx.x;
    int b  = widx >> 6;
    int wi = (widx >> 3) & 7;
    int wj = widx & 7;
    int tid  = threadIdx.x;
    int warp = tid >> 5, lane = tid & 31;

    // ---- load 49 tokens (rows 49..63 zero) ----
    for (int idx = tid; idx < 64*CC; idx += 512) {
        int n = idx / CC, c = idx % CC;
        float v = 0.f;
        if (n < NTOK) {
            int h  = (n/7)*8 + wi;
            int w2 = (n%7)*8 + wj;
            v = sc[(((size_t)b*HH + h)*WW + w2)*CC + c];
        }
        s_x[idx] = v;
    }
    __syncthreads();

    // ---- LayerNorm per token ----
    for (int n = warp; n < NTOK; n += 16) {
        float vals[6]; float s = 0.f;
#pragma unroll
        for (int u = 0; u < 6; u++) { vals[u] = s_x[n*CC + lane + u*32]; s += vals[u]; }
#pragma unroll
        for (int o = 16; o; o >>= 1) s += __shfl_xor_sync(0xffffffffu, s, o);
        float m = s * (1.f/192.f);
        float vv = 0.f;
#pragma unroll
        for (int u = 0; u < 6; u++) { float d = vals[u]-m; vv += d*d; }
#pragma unroll
        for (int o = 16; o; o >>= 1) vv += __shfl_xor_sync(0xffffffffu, vv, o);
        float rs = rsqrtf(vv*(1.f/192.f) + 1e-5f);
#pragma unroll
        for (int u = 0; u < 6; u++) {
            int c = lane + u*32;
            s_x[n*CC + c] = (vals[u]-m)*rs*n1g[c] + n1b[c];
        }
    }
    __syncthreads();

    int tc = tid & 15, tr = tid >> 4;   // tr in 0..31
    int j0 = tc*4;

    // ---- qkv GEMM: [49,192] x [192,576], f32x2 packed ----
    for (int jt = 0; jt < 9; jt++) {
        for (int i = tid; i < 192*64; i += 512) {
            int k = i >> 6, j = i & 63;
            s_w[i] = qkvw[k*576 + jt*64 + j];
        }
        __syncthreads();
        float2 acc[2][2];
        {
            float4 bias4 = *(const float4*)&qkvb[jt*64 + j0];
#pragma unroll
            for (int m = 0; m < 2; m++) {
                acc[m][0] = make_float2(bias4.x, bias4.y);
                acc[m][1] = make_float2(bias4.z, bias4.w);
            }
        }
#pragma unroll 4
        for (int k = 0; k < CC; k++) {
            float4 bv = *(const float4*)&s_w[k*64 + j0];
            float2 b01 = make_float2(bv.x, bv.y);
            float2 b23 = make_float2(bv.z, bv.w);
#pragma unroll
            for (int m = 0; m < 2; m++) {
                float a = s_x[(tr + 32*m)*CC + k];
                float2 a2 = make_float2(a, a);
                ffma2(acc[m][0], a2, b01);
                ffma2(acc[m][1], a2, b23);
            }
        }
#pragma unroll
        for (int m = 0; m < 2; m++) {
            int n = tr + 32*m;
            if (n < NTOK) {
                *(float4*)&s_qkv[n*576 + jt*64 + j0] =
                    make_float4(acc[m][0].x, acc[m][0].y, acc[m][1].x, acc[m][1].y);
            }
        }
        __syncthreads();
    }

    // ---- attention, 2 heads per pass ----
    const float scale = 0.17677669529663687f;  // 32^-0.5
    float* s_kt = s_w;                          // [2][32][50]
    for (int hp = 0; hp < 3; hp++) {
        int hh2 = hp*2;
        // transpose K (row stride 50 -> conflict free)
        for (int idx = tid; idx < 2*NTOK*HDIM; idx += 512) {
            int hl = (idx >= NTOK*HDIM) ? 1 : 0;
            int r  = idx - hl*NTOK*HDIM;
            int j2 = r >> 5, d = r & 31;
            s_kt[hl*1600 + d*50 + j2] = s_qkv[j2*576 + 6 + (hh2+hl) + d*18];
        }
        __syncthreads();
        // scores
        for (int idx = tid; idx < 2*NTOK*NTOK; idx += 512) {
            int hl = (idx >= NTOK*NTOK) ? 1 : 0;
            int r  = idx - hl*NTOK*NTOK;
            int i2 = r / NTOK, j2 = r % NTOK;
            const float* q  = &s_qkv[i2*576 + hh2 + hl];
            const float* kt = &s_kt[hl*1600 + j2];
            float s = 0.f;
#pragma unroll
            for (int d = 0; d < HDIM; d++)
                s = fmaf(q[d*18], kt[d*50], s);
            s_p[hl*2548 + i2*52 + j2] = s * scale;
        }
        __syncthreads();
        // softmax rows (2*49 rows over 16 warps)
        for (int n = warp; n < 2*NTOK; n += 16) {
            int hl = (n >= NTOK) ? 1 : 0;
            int i2 = n - hl*NTOK;
            float* row = &s_p[hl*2548 + i2*52];
            float v1 = row[lane];
            bool has2 = (lane + 32) < NTOK;
            float v2 = has2 ? row[lane + 32] : -INFINITY;
            float mx = fmaxf(v1, v2);
#pragma unroll
            for (int o = 16; o; o >>= 1) mx = fmaxf(mx, __shfl_xor_sync(0xffffffffu, mx, o));
            float e1 = expf(v1 - mx);
            float e2 = has2 ? expf(v2 - mx) : 0.f;
            float ss = e1 + e2;
#pragma unroll
            for (int o = 16; o; o >>= 1) ss += __shfl_xor_sync(0xffffffffu, ss, o);
            float inv = 1.f / ss;
            row[lane] = e1 * inv;
            if (has2) row[lane + 32] = e2 * inv;
        }
        __syncthreads();
        // out = P @ V -> s_x[n][h*32+d]
        for (int idx = tid; idx < 2*NTOK*HDIM; idx += 512) {
            int hl = (idx >= NTOK*HDIM) ? 1 : 0;
            int r  = idx - hl*NTOK*HDIM;
            int i2 = r >> 5, d = r & 31;
            const float* vv = &s_qkv[d*18 + 12 + hh2 + hl];
            const float* pp = &s_p[hl*2548 + i2*52];
            float s = 0.f;
#pragma unroll
            for (int j2 = 0; j2 < NTOK; j2++)
                s = fmaf(pp[j2], vv[j2*576], s);
            s_x[i2*CC + (hh2+hl)*HDIM + d] = s;
        }
        __syncthreads();
    }

    // ---- proj GEMM [49,192]x[192,192] + residual, f32x2 packed ----
    for (int jt = 0; jt < 3; jt++) {
        for (int i = tid; i < 192*64; i += 512) {
            int k = i >> 6, j = i & 63;
            s_w[i] = projw[k*CC + jt*64 + j];
        }
        __syncthreads();
        float2 acc[2][2];
        {
            float4 bias4 = *(const float4*)&projb[jt*64 + j0];
#pragma unroll
            for (int m = 0; m < 2; m++) {
                acc[m][0] = make_float2(bias4.x, bias4.y);
                acc[m][1] = make_float2(bias4.z, bias4.w);
            }
        }
#pragma unroll 4
        for (int k = 0; k < CC; k++) {
            float4 bv = *(const float4*)&s_w[k*64 + j0];
            float2 b01 = make_float2(bv.x, bv.y);
            float2 b23 = make_float2(bv.z, bv.w);
#pragma unroll
            for (int m = 0; m < 2; m++) {
                float a = s_x[(tr + 32*m)*CC + k];
                float2 a2 = make_float2(a, a);
                ffma2(acc[m][0], a2, b01);
                ffma2(acc[m][1], a2, b23);
            }
        }
#pragma unroll
        for (int m = 0; m < 2; m++) {
            int n = tr + 32*m;
            if (n < NTOK) {
                int h  = (n/7)*8 + wi;
                int w2 = (n%7)*8 + wj;
                size_t gbase = (((size_t)b*HH + h)*WW + w2)*CC + jt*64 + j0;
                float4 r4 = *(const float4*)&sc[gbase];
                float4 o4;
                o4.x = r4.x + acc[m][0].x;
                o4.y = r4.y + acc[m][0].y;
                o4.z = r4.z + acc[m][1].x;
                o4.w = r4.w + acc[m][1].y;
                *(float4*)&yout[gbase] = o4;
            }
        }
        __syncthreads();
    }
}

// ---------------------------------------------------------------------------
// Fused LN2 + MLP (fc1 -> gelu -> fc2) + residual.  64 tokens per block.
// ---------------------------------------------------------------------------
#define MLP_SMEM_FLOATS (64*192 + 64*64 + 192*64)
#define MLP_SMEM_BYTES  (MLP_SMEM_FLOATS*4)

__global__ __launch_bounds__(256) void mlp_kernel(
    const float* __restrict__ y2,
    const float* __restrict__ n2g, const float* __restrict__ n2b,
    const float* __restrict__ fc1w, const float* __restrict__ fc1b,
    const float* __restrict__ fc2w, const float* __restrict__ fc2b,
    float* __restrict__ out)
{
    extern __shared__ float sm[];
    float* s_x = sm;            // [64][192]
    float* s_h = s_x + 64*192;  // [64][64]
    float* s_w = s_h + 64*64;   // [192][64] fc1 tile / [64][192] fc2 tile

    int tid = threadIdx.x;
    size_t t0 = (size_t)blockIdx.x * 64;

    for (int i = tid; i < 64*CC; i += 256) s_x[i] = y2[t0*CC + i];
    __syncthreads();

    int warp = tid >> 5, lane = tid & 31;
    for (int n = warp; n < 64; n += 8) {
        float vals[6]; float s = 0.f;
#pragma unroll
        for (int u = 0; u < 6; u++) { vals[u] = s_x[n*CC + lane + u*32]; s += vals[u]; }
#pragma unroll
        for (int o = 16; o; o >>= 1) s += __shfl_xor_sync(0xffffffffu, s, o);
        float m = s * (1.f/192.f);
        float vv = 0.f;
#pragma unroll
        for (int u = 0; u < 6; u++) { float d = vals[u]-m; vv += d*d; }
#pragma unroll
        for (int o = 16; o; o >>= 1) vv += __shfl_xor_sync(0xffffffffu, vv, o);
        float rs = rsqrtf(vv*(1.f/192.f) + 1e-5f);
#pragma unroll
        for (int u = 0; u < 6; u++) {
            int c = lane + u*32;
            s_x[n*CC + c] = (vals[u]-m)*rs*n2g[c] + n2b[c];
        }
    }
    __syncthreads();

    int tc = tid & 15, tr = tid >> 4;
    float2 acc[4][6];           // 4 rows x 12 cols (6 packed pairs)
#pragma unroll
    for (int r = 0; r < 4; r++)
#pragma unroll
        for (int g = 0; g < 6; g++) acc[r][g] = make_float2(0.f, 0.f);

    for (int ht = 0; ht < 12; ht++) {
        // fc1 weight tile [192][64]
        for (int i = tid; i < 192*64; i += 256) {
            int k = i >> 6, j = i & 63;
            s_w[i] = fc1w[k*HIDDEN + ht*64 + j];
        }
        __syncthreads();
        float2 hacc[4][2];
        {
            float4 bias4 = *(const float4*)&fc1b[ht*64 + tc*4];
#pragma unroll
            for (int r = 0; r < 4; r++) {
                hacc[r][0] = make_float2(bias4.x, bias4.y);
                hacc[r][1] = make_float2(bias4.z, bias4.w);
            }
        }
#pragma unroll 4
        for (int k = 0; k < CC; k++) {
            float4 bv = *(const float4*)&s_w[k*64 + tc*4];
            float2 b01 = make_float2(bv.x, bv.y);
            float2 b23 = make_float2(bv.z, bv.w);
#pragma unroll
            for (int r = 0; r < 4; r++) {
                float a = s_x[(tr*4 + r)*CC + k];
                float2 a2 = make_float2(a, a);
                ffma2(hacc[r][0], a2, b01);
                ffma2(hacc[r][1], a2, b23);
            }
        }
#pragma unroll
        for (int r = 0; r < 4; r++) {
            float4 o4;
            o4.x = gelu_exact(hacc[r][0].x);
            o4.y = gelu_exact(hacc[r][0].y);
            o4.z = gelu_exact(hacc[r][1].x);
            o4.w = gelu_exact(hacc[r][1].y);
            *(float4*)&s_h[(tr*4 + r)*64 + tc*4] = o4;
        }
        __syncthreads();
        // fc2 weight tile [64][192]
        for (int i = tid; i < 64*CC; i += 256) {
            int k = i / CC, c = i % CC;
            s_w[i] = fc2w[(ht*64 + k)*CC + c];
        }
        __syncthreads();
#pragma unroll 2
        for (int k = 0; k < 64; k++) {
            float2 a2[4];
#pragma unroll
            for (int r = 0; r < 4; r++) {
                float a = s_h[(tr*4 + r)*64 + k];
                a2[r] = make_float2(a, a);
            }
#pragma unroll
            for (int g3 = 0; g3 < 3; g3++) {
                float4 bv = *(const float4*)&s_w[k*CC + g3*64 + tc*4];
                float2 b01 = make_float2(bv.x, bv.y);
                float2 b23 = make_float2(bv.z, bv.w);
#pragma unroll
                for (int r = 0; r < 4; r++) {
                    ffma2(acc[r][g3*2+0], a2[r], b01);
                    ffma2(acc[r][g3*2+1], a2[r], b23);
                }
            }
        }
        __syncthreads();
    }

#pragma unroll
    for (int r = 0; r < 4; r++) {
        size_t row = t0 + tr*4 + r;
#pragma unroll
        for (int g3 = 0; g3 < 3; g3++) {
            int col = g3*64 + tc*4;
            float4 res = *(const float4*)&y2[row*CC + col];
            float4 bb  = *(const float4*)&fc2b[col];
            float4 o4;
            o4.x = res.x + bb.x + acc[r][g3*2+0].x;
            o4.y = res.y + bb.y + acc[r][g3*2+0].y;
            o4.z = res.z + bb.z + acc[r][g3*2+1].x;
            o4.w = res.w + bb.w + acc[r][g3*2+1].y;
            *(float4*)&out[row*CC + col] = o4;
        }
    }
}

// ---------------------------------------------------------------------------
extern "C" void kernel_launch(void* const* d_in, const int* in_sizes, int n_in,
                              void* d_out, int out_size)
{
    int p = 0;
    const float* x = (const float*)d_in[p++];
    while (p < n_in && in_sizes[p] == 1) p++;   // skip scalar H, W if present
    const float* cpe0_w = (const float*)d_in[p++];
    const float* cpe0_b = (const float*)d_in[p++];
    const float* cpe1_w = (const float*)d_in[p++];
    const float* cpe1_b = (const float*)d_in[p++];
    const float* n1_g   = (const float*)d_in[p++];
    const float* n1_b   = (const float*)d_in[p++];
    const float* qkv_w  = (const float*)d_in[p++];
    const float* qkv_b  = (const float*)d_in[p++];
    const float* proj_w = (const float*)d_in[p++];
    const float* proj_b = (const float*)d_in[p++];
    const float* n2_g   = (const float*)d_in[p++];
    const float* n2_b   = (const float*)d_in[p++];
    const float* fc1_w  = (const float*)d_in[p++];
    const float* fc1_b  = (const float*)d_in[p++];
    const float* fc2_w  = (const float*)d_in[p++];
    const float* fc2_b  = (const float*)d_in[p++];

    float *b0, *b1, *b2;
    cudaGetSymbolAddress((void**)&b0, g_buf0);
    cudaGetSymbolAddress((void**)&b1, g_buf1);
    cudaGetSymbolAddress((void**)&b2, g_buf2);

    cudaFuncSetAttribute(attn_kernel, cudaFuncAttributeMaxDynamicSharedMemorySize,
                         ATTN_SMEM_BYTES);
    cudaFuncSetAttribute(mlp_kernel, cudaFuncAttributeMaxDynamicSharedMemorySize,
                         MLP_SMEM_BYTES);

    dim3 gcpe(HH, BATCH);
    cpe_kernel<<<gcpe, CC>>>(x, cpe0_w, cpe0_b, b0);
    attn_kernel<<<BATCH*64, 512, ATTN_SMEM_BYTES>>>(b0, n1_g, n1_b, qkv_w, qkv_b,
                                                    proj_w, proj_b, b1);
    cpe_kernel<<<gcpe, CC>>>(b1, cpe1_w, cpe1_b, b2);
    mlp_kernel<<<TOKENS/64, 256, MLP_SMEM_BYTES>>>(b2, n2_g, n2_b, fc1_w, fc1_b,
                                                   fc2_w, fc2_b, (float*)d_out);
}

// round 3
// speedup vs baseline: 1.9681x; 1.1209x over previous
#include <cuda_runtime.h>
#include <math.h>

#define BATCH 32
#define HH 56
#define WW 56
#define CC 192
#define NHEAD 6
#define HDIM 32
#define NTOK 49
#define HIDDEN 768
#define TOKENS (BATCH*HH*WW)   // 100352

// Scratch (device globals — no runtime allocation allowed)
__device__ float g_buf0[TOKENS*CC];      // shortcut (after cpe0)
__device__ float g_buf1[TOKENS*CC];      // y (after attn residual)
__device__ float g_buf2[TOKENS*CC];      // y2 (after cpe1)
__device__ float g_xn  [TOKENS*CC];      // LN output (reused)
__device__ float g_attn[TOKENS*CC];      // attention output (pre-proj)
__device__ float g_qkv [TOKENS*3*CC];    // qkv
__device__ float g_h   [TOKENS*HIDDEN];  // mlp hidden

__device__ __forceinline__ float gelu_exact(float x) {
    return 0.5f * x * (1.f + erff(x * 0.7071067811865475f));
}

// Packed dual-fp32 FMA: d.x += a.x*b.x ; d.y += a.y*b.y  (one instruction)
__device__ __forceinline__ void ffma2(float2& d, float2 a, float2 b) {
    asm("fma.rn.f32x2 %0, %1, %2, %0;"
        : "+l"(reinterpret_cast<unsigned long long&>(d))
        : "l"(reinterpret_cast<unsigned long long&>(a)),
          "l"(reinterpret_cast<unsigned long long&>(b)));
}

// ---------------------------------------------------------------------------
// Depthwise 3x3 conv (SAME) + residual
// ---------------------------------------------------------------------------
__global__ void cpe_kernel(const float* __restrict__ in,
                           const float* __restrict__ wgt,
                           const float* __restrict__ bias,
                           float* __restrict__ out)
{
    int h = blockIdx.x;
    int b = blockIdx.y;
    int c = threadIdx.x;
    float kw[9];
#pragma unroll
    for (int i = 0; i < 9; i++) kw[i] = wgt[c*9 + i];
    float bb = bias[c];
    const float* base  = in  + ((size_t)b*HH*WW)*CC + c;
    float*       obase = out + ((size_t)b*HH*WW)*CC + c;

    float colL[3], colM[3], colR[3];
#pragma unroll
    for (int dy = 0; dy < 3; dy++) {
        colL[dy] = 0.f;
        int hy = h + dy - 1;
        colM[dy] = (hy >= 0 && hy < HH) ? base[(size_t)(hy*WW)*CC] : 0.f;
    }
    for (int x = 0; x < WW; x++) {
#pragma unroll
        for (int dy = 0; dy < 3; dy++) {
            int hy = h + dy - 1;
            colR[dy] = (x+1 < WW && hy >= 0 && hy < HH)
                       ? base[(size_t)(hy*WW + x + 1)*CC] : 0.f;
        }
        float acc = bb;
#pragma unroll
        for (int dy = 0; dy < 3; dy++) {
            acc = fmaf(kw[dy*3+0], colL[dy], acc);
            acc = fmaf(kw[dy*3+1], colM[dy], acc);
            acc = fmaf(kw[dy*3+2], colR[dy], acc);
        }
        obase[(size_t)(h*WW + x)*CC] = colM[1] + acc;
#pragma unroll
        for (int dy = 0; dy < 3; dy++) { colL[dy] = colM[dy]; colM[dy] = colR[dy]; }
    }
}

// ---------------------------------------------------------------------------
// Per-token LayerNorm: one warp per token
// ---------------------------------------------------------------------------
__global__ void ln_kernel(const float* __restrict__ in,
                          const float* __restrict__ g, const float* __restrict__ b,
                          float* __restrict__ out)
{
    int tok  = blockIdx.x*8 + (threadIdx.x >> 5);
    int lane = threadIdx.x & 31;
    const float* p = in  + (size_t)tok*CC;
    float*       o = out + (size_t)tok*CC;
    float vals[6]; float s = 0.f;
#pragma unroll
    for (int u = 0; u < 6; u++) { vals[u] = p[lane + u*32]; s += vals[u]; }
#pragma unroll
    for (int off = 16; off; off >>= 1) s += __shfl_xor_sync(0xffffffffu, s, off);
    float m = s * (1.f/192.f);
    float vv = 0.f;
#pragma unroll
    for (int u = 0; u < 6; u++) { float d = vals[u]-m; vv += d*d; }
#pragma unroll
    for (int off = 16; off; off >>= 1) vv += __shfl_xor_sync(0xffffffffu, vv, off);
    float rs = rsqrtf(vv*(1.f/192.f) + 1e-5f);
#pragma unroll
    for (int u = 0; u < 6; u++) {
        int c = lane + u*32;
        o[c] = (vals[u]-m)*rs*g[c] + b[c];
    }
}

// ---------------------------------------------------------------------------
// Generic GEMM: out[M,N] = A[M,KTOT] @ W[KTOT,N] + bias (+gelu) (+residual)
// Block tile 128 rows x 192 cols; 384 threads; 8x8 register tile per thread.
// A staged TRANSPOSED in smem (stride 132), W staged (stride 196); both
// operands read as float4 -> 64 smem bytes per k for 64 FMA (1.0 FMA/B).
// ---------------------------------------------------------------------------
#define GEMM_SMEM_FLOATS (64*132 + 64*196)
#define GEMM_SMEM_BYTES  (GEMM_SMEM_FLOATS*4)

template<int KTOT, bool GELU, bool RES>
__global__ __launch_bounds__(384) void gemm_kernel(
    const float* __restrict__ A, const float* __restrict__ W,
    const float* __restrict__ bias, const float* __restrict__ res,
    float* __restrict__ out, int N)
{
    extern __shared__ float sm[];
    float* sA = sm;            // [64][132] transposed A chunk
    float* sW = sm + 64*132;   // [64][196]

    int tid = threadIdx.x;
    int rg = tid / 24;         // 0..15 row group
    int cg = tid % 24;         // 0..23 col group
    int row0 = blockIdx.x * 128;
    int col0 = blockIdx.y * 192;

    float2 acc[8][4];
#pragma unroll
    for (int i = 0; i < 8; i++)
#pragma unroll
        for (int j = 0; j < 4; j++) acc[i][j] = make_float2(0.f, 0.f);

    for (int k0 = 0; k0 < KTOT; k0 += 64) {
        // A chunk, transposed into smem (coalesced global reads along k)
        for (int idx = tid; idx < 64*128; idx += 384) {
            int k = idx & 63, r = idx >> 6;
            sA[k*132 + r] = A[(size_t)(row0 + r)*KTOT + k0 + k];
        }
        // W chunk (coalesced along columns)
#pragma unroll
        for (int i = 0; i < 32; i++) {
            int idx = tid + i*384;
            int k = idx / 192, c = idx % 192;
            sW[k*196 + c] = W[(size_t)(k0 + k)*N + col0 + c];
        }
        __syncthreads();
#pragma unroll 2
        for (int k = 0; k < 64; k++) {
            const float* ap = &sA[k*132 + rg*8];
            float4 a0 = *(const float4*)ap;
            float4 a1 = *(const float4*)(ap + 4);
            const float* wp = &sW[k*196 + cg*8];
            float4 b0 = *(const float4*)wp;
            float4 b1 = *(const float4*)(wp + 4);
            float2 bp[4];
            bp[0] = make_float2(b0.x, b0.y);
            bp[1] = make_float2(b0.z, b0.w);
            bp[2] = make_float2(b1.x, b1.y);
            bp[3] = make_float2(b1.z, b1.w);
            float ar[8] = {a0.x, a0.y, a0.z, a0.w, a1.x, a1.y, a1.z, a1.w};
#pragma unroll
            for (int i = 0; i < 8; i++) {
                float2 a2 = make_float2(ar[i], ar[i]);
#pragma unroll
                for (int j = 0; j < 4; j++) ffma2(acc[i][j], a2, bp[j]);
            }
        }
        __syncthreads();
    }

    // epilogue
    float4 bb0 = *(const float4*)&bias[col0 + cg*8];
    float4 bb1 = *(const float4*)&bias[col0 + cg*8 + 4];
    float bsc[8] = {bb0.x, bb0.y, bb0.z, bb0.w, bb1.x, bb1.y, bb1.z, bb1.w};
#pragma unroll
    for (int i = 0; i < 8; i++) {
        size_t o = (size_t)(row0 + rg*8 + i)*N + col0 + cg*8;
        float v[8];
        v[0] = acc[i][0].x + bsc[0]; v[1] = acc[i][0].y + bsc[1];
        v[2] = acc[i][1].x + bsc[2]; v[3] = acc[i][1].y + bsc[3];
        v[4] = acc[i][2].x + bsc[4]; v[5] = acc[i][2].y + bsc[5];
        v[6] = acc[i][3].x + bsc[6]; v[7] = acc[i][3].y + bsc[7];
        if (GELU) {
#pragma unroll
            for (int j = 0; j < 8; j++) v[j] = gelu_exact(v[j]);
        }
        if (RES) {
            float4 r0 = *(const float4*)&res[o];
            float4 r1 = *(const float4*)&res[o + 4];
            v[0] += r0.x; v[1] += r0.y; v[2] += r0.z; v[3] += r0.w;
            v[4] += r1.x; v[5] += r1.y; v[6] += r1.z; v[7] += r1.w;
        }
        *(float4*)&out[o]     = make_float4(v[0], v[1], v[2], v[3]);
        *(float4*)&out[o + 4] = make_float4(v[4], v[5], v[6], v[7]);
    }
}

// ---------------------------------------------------------------------------
// Attention core: per window, scores -> softmax -> PV.  Reads gathered qkv,
// writes attention output in token-major layout (window-reverse fused).
// qkv column (faithful (d,3,h) split): q: d*18+h, k: d*18+6+h, v: d*18+12+h
// ---------------------------------------------------------------------------
#define ATTN_SMEM_FLOATS (49*576 + 2*32*50 + 2*49*52)
#define ATTN_SMEM_BYTES  (ATTN_SMEM_FLOATS*4)

__global__ __launch_bounds__(512) void attn_core(
    const float* __restrict__ qkv, float* __restrict__ aout)
{
    extern __shared__ float sm[];
    float* s_qkv = sm;                 // [49][576]
    float* s_kt  = s_qkv + 49*576;     // [2][32][50]
    float* s_p   = s_kt + 2*1600;      // [2][49][52]

    int widx = blockIdx.x;
    int b  = widx >> 6;
    int wi = (widx >> 3) & 7;
    int wj = widx & 7;
    int tid  = threadIdx.x;
    int warp = tid >> 5, lane = tid & 31;

    // gather the window's qkv rows
    for (int idx = tid; idx < NTOK*576; idx += 512) {
        int n = idx / 576, c = idx % 576;
        int h  = (n/7)*8 + wi;
        int w2 = (n%7)*8 + wj;
        s_qkv[idx] = qkv[((size_t)(b*HH + h)*WW + w2)*576 + c];
    }
    __syncthreads();

    const float scale = 0.17677669529663687f;  // 32^-0.5
    for (int hp = 0; hp < 3; hp++) {
        int hh2 = hp*2;
        // transpose K (row stride 50 -> conflict free)
        for (int idx = tid; idx < 2*NTOK*HDIM; idx += 512) {
            int hl = (idx >= NTOK*HDIM) ? 1 : 0;
            int r  = idx - hl*NTOK*HDIM;
            int j2 = r >> 5, d = r & 31;
            s_kt[hl*1600 + d*50 + j2] = s_qkv[j2*576 + 6 + (hh2+hl) + d*18];
        }
        __syncthreads();
        // scores
        for (int idx = tid; idx < 2*NTOK*NTOK; idx += 512) {
            int hl = (idx >= NTOK*NTOK) ? 1 : 0;
            int r  = idx - hl*NTOK*NTOK;
            int i2 = r / NTOK, j2 = r % NTOK;
            const float* q  = &s_qkv[i2*576 + hh2 + hl];
            const float* kt = &s_kt[hl*1600 + j2];
            float s = 0.f;
#pragma unroll
            for (int d = 0; d < HDIM; d++)
                s = fmaf(q[d*18], kt[d*50], s);
            s_p[hl*2548 + i2*52 + j2] = s * scale;
        }
        __syncthreads();
        // softmax rows
        for (int n = warp; n < 2*NTOK; n += 16) {
            int hl = (n >= NTOK) ? 1 : 0;
            int i2 = n - hl*NTOK;
            float* row = &s_p[hl*2548 + i2*52];
            float v1 = row[lane];
            bool has2 = (lane + 32) < NTOK;
            float v2 = has2 ? row[lane + 32] : -INFINITY;
            float mx = fmaxf(v1, v2);
#pragma unroll
            for (int o = 16; o; o >>= 1) mx = fmaxf(mx, __shfl_xor_sync(0xffffffffu, mx, o));
            float e1 = expf(v1 - mx);
            float e2 = has2 ? expf(v2 - mx) : 0.f;
            float ss = e1 + e2;
#pragma unroll
            for (int o = 16; o; o >>= 1) ss += __shfl_xor_sync(0xffffffffu, ss, o);
            float inv = 1.f / ss;
            row[lane] = e1 * inv;
            if (has2) row[lane + 32] = e2 * inv;
        }
        __syncthreads();
        // out = P @ V -> global (token-major, window-reverse fused)
        for (int idx = tid; idx < 2*NTOK*HDIM; idx += 512) {
            int hl = (idx >= NTOK*HDIM) ? 1 : 0;
            int r  = idx - hl*NTOK*HDIM;
            int i2 = r >> 5, d = r & 31;
            const float* vv = &s_qkv[d*18 + 12 + hh2 + hl];
            const float* pp = &s_p[hl*2548 + i2*52];
            float s = 0.f;
#pragma unroll
            for (int j2 = 0; j2 < NTOK; j2++)
                s = fmaf(pp[j2], vv[j2*576], s);
            int h  = (i2/7)*8 + wi;
            int w2 = (i2%7)*8 + wj;
            aout[((size_t)(b*HH + h)*WW + w2)*CC + (hh2+hl)*HDIM + d] = s;
        }
        __syncthreads();
    }
}

// ---------------------------------------------------------------------------
extern "C" void kernel_launch(void* const* d_in, const int* in_sizes, int n_in,
                              void* d_out, int out_size)
{
    int p = 0;
    const float* x = (const float*)d_in[p++];
    while (p < n_in && in_sizes[p] == 1) p++;   // skip scalar H, W if present
    const float* cpe0_w = (const float*)d_in[p++];
    const float* cpe0_b = (const float*)d_in[p++];
    const float* cpe1_w = (const float*)d_in[p++];
    const float* cpe1_b = (const float*)d_in[p++];
    const float* n1_g   = (const float*)d_in[p++];
    const float* n1_b   = (const float*)d_in[p++];
    const float* qkv_w  = (const float*)d_in[p++];
    const float* qkv_b  = (const float*)d_in[p++];
    const float* proj_w = (const float*)d_in[p++];
    const float* proj_b = (const float*)d_in[p++];
    const float* n2_g   = (const float*)d_in[p++];
    const float* n2_b   = (const float*)d_in[p++];
    const float* fc1_w  = (const float*)d_in[p++];
    const float* fc1_b  = (const float*)d_in[p++];
    const float* fc2_w  = (const float*)d_in[p++];
    const float* fc2_b  = (const float*)d_in[p++];

    float *b0, *b1, *b2, *xn, *attn, *qkv, *hbuf;
    cudaGetSymbolAddress((void**)&b0, g_buf0);
    cudaGetSymbolAddress((void**)&b1, g_buf1);
    cudaGetSymbolAddress((void**)&b2, g_buf2);
    cudaGetSymbolAddress((void**)&xn, g_xn);
    cudaGetSymbolAddress((void**)&attn, g_attn);
    cudaGetSymbolAddress((void**)&qkv, g_qkv);
    cudaGetSymbolAddress((void**)&hbuf, g_h);

    cudaFuncSetAttribute(gemm_kernel<192,false,false>,
                         cudaFuncAttributeMaxDynamicSharedMemorySize, GEMM_SMEM_BYTES);
    cudaFuncSetAttribute(gemm_kernel<192,false,true>,
                         cudaFuncAttributeMaxDynamicSharedMemorySize, GEMM_SMEM_BYTES);
    cudaFuncSetAttribute(gemm_kernel<192,true,false>,
                         cudaFuncAttributeMaxDynamicSharedMemorySize, GEMM_SMEM_BYTES);
    cudaFuncSetAttribute(gemm_kernel<768,false,true>,
                         cudaFuncAttributeMaxDynamicSharedMemorySize, GEMM_SMEM_BYTES);
    cudaFuncSetAttribute(attn_core,
                         cudaFuncAttributeMaxDynamicSharedMemorySize, ATTN_SMEM_BYTES);

    dim3 gcpe(HH, BATCH);
    const int MB = TOKENS/128;   // 784 row blocks

    cpe_kernel<<<gcpe, CC>>>(x, cpe0_w, cpe0_b, b0);
    ln_kernel<<<TOKENS/8, 256>>>(b0, n1_g, n1_b, xn);
    gemm_kernel<192,false,false><<<dim3(MB,3), 384, GEMM_SMEM_BYTES>>>(
        xn, qkv_w, qkv_b, nullptr, qkv, 576);
    attn_core<<<BATCH*64, 512, ATTN_SMEM_BYTES>>>(qkv, attn);
    gemm_kernel<192,false,true><<<dim3(MB,1), 384, GEMM_SMEM_BYTES>>>(
        attn, proj_w, proj_b, b0, b1, 192);
    cpe_kernel<<<gcpe, CC>>>(b1, cpe1_w, cpe1_b, b2);
    ln_kernel<<<TOKENS/8, 256>>>(b2, n2_g, n2_b, xn);
    gemm_kernel<192,true,false><<<dim3(MB,4), 384, GEMM_SMEM_BYTES>>>(
        xn, fc1_w, fc1_b, nullptr, hbuf, 768);
    gemm_kernel<768,false,true><<<dim3(MB,1), 384, GEMM_SMEM_BYTES>>>(
        hbuf, fc2_w, fc2_b, b2, (float*)d_out, 192);
}

// round 4
// speedup vs baseline: 2.3785x; 1.2086x over previous
#include <cuda_runtime.h>
#include <math.h>

#define BATCH 32
#define HH 56
#define WW 56
#define CC 192
#define NHEAD 6
#define HDIM 32
#define NTOK 49
#define HIDDEN 768
#define TOKENS (BATCH*HH*WW)   // 100352

// Scratch (device globals — no runtime allocation allowed)
__device__ float g_buf0[TOKENS*CC];      // shortcut (after cpe0)
__device__ float g_buf1[TOKENS*CC];      // y (after attn residual)
__device__ float g_buf2[TOKENS*CC];      // y2 (after cpe1)
__device__ float g_xn  [TOKENS*CC];      // LN output (reused)
__device__ float g_attn[TOKENS*CC];      // attention output (pre-proj)
__device__ float g_qkv [TOKENS*3*CC];    // qkv in [tok][kqv][head][32] layout
__device__ float g_h   [TOKENS*HIDDEN];  // mlp hidden
__device__ float g_wp  [CC*3*CC];        // permuted qkv weight
__device__ float g_bp  [3*CC];           // permuted qkv bias

__device__ __forceinline__ float gelu_exact(float x) {
    return 0.5f * x * (1.f + erff(x * 0.7071067811865475f));
}

// Packed dual-fp32 FMA: d.x += a.x*b.x ; d.y += a.y*b.y  (one instruction)
__device__ __forceinline__ void ffma2(float2& d, float2 a, float2 b) {
    asm("fma.rn.f32x2 %0, %1, %2, %0;"
        : "+l"(reinterpret_cast<unsigned long long&>(d))
        : "l"(reinterpret_cast<unsigned long long&>(a)),
          "l"(reinterpret_cast<unsigned long long&>(b)));
}

// ---------------------------------------------------------------------------
// One-shot permutation of qkv weight/bias columns:
// dst col = kk*192 + h*32 + d   <-  src col = d*18 + kk*6 + h  (faithful (d k h))
// ---------------------------------------------------------------------------
__global__ void permute_qkv_w(const float* __restrict__ W,
                              const float* __restrict__ bias,
                              float* __restrict__ Wp, float* __restrict__ bp)
{
    int idx = blockIdx.x*256 + threadIdx.x;   // grid covers 192*576
    int dst = idx % 576, k = idx / 576;
    int kk = dst / 192, rem = dst % 192;
    int h = rem / 32, d = rem % 32;
    int src = d*18 + kk*6 + h;
    Wp[idx] = W[k*576 + src];
    if (idx < 576) bp[idx] = bias[src];
}

// ---------------------------------------------------------------------------
// Depthwise 3x3 conv (SAME) + residual
// ---------------------------------------------------------------------------
__global__ void cpe_kernel(const float* __restrict__ in,
                           const float* __restrict__ wgt,
                           const float* __restrict__ bias,
                           float* __restrict__ out)
{
    int h = blockIdx.x;
    int b = blockIdx.y;
    int c = threadIdx.x;
    float kw[9];
#pragma unroll
    for (int i = 0; i < 9; i++) kw[i] = wgt[c*9 + i];
    float bb = bias[c];
    const float* base  = in  + ((size_t)b*HH*WW)*CC + c;
    float*       obase = out + ((size_t)b*HH*WW)*CC + c;

    float colL[3], colM[3], colR[3];
#pragma unroll
    for (int dy = 0; dy < 3; dy++) {
        colL[dy] = 0.f;
        int hy = h + dy - 1;
        colM[dy] = (hy >= 0 && hy < HH) ? base[(size_t)(hy*WW)*CC] : 0.f;
    }
    for (int x = 0; x < WW; x++) {
#pragma unroll
        for (int dy = 0; dy < 3; dy++) {
            int hy = h + dy - 1;
            colR[dy] = (x+1 < WW && hy >= 0 && hy < HH)
                       ? base[(size_t)(hy*WW + x + 1)*CC] : 0.f;
        }
        float acc = bb;
#pragma unroll
        for (int dy = 0; dy < 3; dy++) {
            acc = fmaf(kw[dy*3+0], colL[dy], acc);
            acc = fmaf(kw[dy*3+1], colM[dy], acc);
            acc = fmaf(kw[dy*3+2], colR[dy], acc);
        }
        obase[(size_t)(h*WW + x)*CC] = colM[1] + acc;
#pragma unroll
        for (int dy = 0; dy < 3; dy++) { colL[dy] = colM[dy]; colM[dy] = colR[dy]; }
    }
}

// ---------------------------------------------------------------------------
// Per-token LayerNorm: one warp per token
// ---------------------------------------------------------------------------
__global__ void ln_kernel(const float* __restrict__ in,
                          const float* __restrict__ g, const float* __restrict__ b,
                          float* __restrict__ out)
{
    int tok  = blockIdx.x*8 + (threadIdx.x >> 5);
    int lane = threadIdx.x & 31;
    const float* p = in  + (size_t)tok*CC;
    float*       o = out + (size_t)tok*CC;
    float vals[6]; float s = 0.f;
#pragma unroll
    for (int u = 0; u < 6; u++) { vals[u] = p[lane + u*32]; s += vals[u]; }
#pragma unroll
    for (int off = 16; off; off >>= 1) s += __shfl_xor_sync(0xffffffffu, s, off);
    float m = s * (1.f/192.f);
    float vv = 0.f;
#pragma unroll
    for (int u = 0; u < 6; u++) { float d = vals[u]-m; vv += d*d; }
#pragma unroll
    for (int off = 16; off; off >>= 1) vv += __shfl_xor_sync(0xffffffffu, vv, off);
    float rs = rsqrtf(vv*(1.f/192.f) + 1e-5f);
#pragma unroll
    for (int u = 0; u < 6; u++) {
        int c = lane + u*32;
        o[c] = (vals[u]-m)*rs*g[c] + b[c];
    }
}

// ---------------------------------------------------------------------------
// Generic GEMM: out[M,N] = A[M,KTOT] @ W[KTOT,N] + bias (+gelu) (+residual)
// Block tile 128 rows x 192 cols; 384 threads; 8x8 register tile per thread.
// ---------------------------------------------------------------------------
#define GEMM_SMEM_FLOATS (64*132 + 64*196)
#define GEMM_SMEM_BYTES  (GEMM_SMEM_FLOATS*4)

template<int KTOT, bool GELU, bool RES>
__global__ __launch_bounds__(384) void gemm_kernel(
    const float* __restrict__ A, const float* __restrict__ W,
    const float* __restrict__ bias, const float* __restrict__ res,
    float* __restrict__ out, int N)
{
    extern __shared__ float sm[];
    float* sA = sm;            // [64][132] transposed A chunk
    float* sW = sm + 64*132;   // [64][196]

    int tid = threadIdx.x;
    int rg = tid / 24;         // 0..15 row group
    int cg = tid % 24;         // 0..23 col group
    int row0 = blockIdx.x * 128;
    int col0 = blockIdx.y * 192;

    float2 acc[8][4];
#pragma unroll
    for (int i = 0; i < 8; i++)
#pragma unroll
        for (int j = 0; j < 4; j++) acc[i][j] = make_float2(0.f, 0.f);

    for (int k0 = 0; k0 < KTOT; k0 += 64) {
        for (int idx = tid; idx < 64*128; idx += 384) {
            int k = idx & 63, r = idx >> 6;
            sA[k*132 + r] = A[(size_t)(row0 + r)*KTOT + k0 + k];
        }
#pragma unroll
        for (int i = 0; i < 32; i++) {
            int idx = tid + i*384;
            int k = idx / 192, c = idx % 192;
            sW[k*196 + c] = W[(size_t)(k0 + k)*N + col0 + c];
        }
        __syncthreads();
#pragma unroll 2
        for (int k = 0; k < 64; k++) {
            const float* ap = &sA[k*132 + rg*8];
            float4 a0 = *(const float4*)ap;
            float4 a1 = *(const float4*)(ap + 4);
            const float* wp = &sW[k*196 + cg*8];
            float4 b0 = *(const float4*)wp;
            float4 b1 = *(const float4*)(wp + 4);
            float2 bp[4];
            bp[0] = make_float2(b0.x, b0.y);
            bp[1] = make_float2(b0.z, b0.w);
            bp[2] = make_float2(b1.x, b1.y);
            bp[3] = make_float2(b1.z, b1.w);
            float ar[8] = {a0.x, a0.y, a0.z, a0.w, a1.x, a1.y, a1.z, a1.w};
#pragma unroll
            for (int i = 0; i < 8; i++) {
                float2 a2 = make_float2(ar[i], ar[i]);
#pragma unroll
                for (int j = 0; j < 4; j++) ffma2(acc[i][j], a2, bp[j]);
            }
        }
        __syncthreads();
    }

    float4 bb0 = *(const float4*)&bias[col0 + cg*8];
    float4 bb1 = *(const float4*)&bias[col0 + cg*8 + 4];
    float bsc[8] = {bb0.x, bb0.y, bb0.z, bb0.w, bb1.x, bb1.y, bb1.z, bb1.w};
#pragma unroll
    for (int i = 0; i < 8; i++) {
        size_t o = (size_t)(row0 + rg*8 + i)*N + col0 + cg*8;
        float v[8];
        v[0] = acc[i][0].x + bsc[0]; v[1] = acc[i][0].y + bsc[1];
        v[2] = acc[i][1].x + bsc[2]; v[3] = acc[i][1].y + bsc[3];
        v[4] = acc[i][2].x + bsc[4]; v[5] = acc[i][2].y + bsc[5];
        v[6] = acc[i][3].x + bsc[6]; v[7] = acc[i][3].y + bsc[7];
        if (GELU) {
#pragma unroll
            for (int j = 0; j < 8; j++) v[j] = gelu_exact(v[j]);
        }
        if (RES) {
            float4 r0 = *(const float4*)&res[o];
            float4 r1 = *(const float4*)&res[o + 4];
            v[0] += r0.x; v[1] += r0.y; v[2] += r0.z; v[3] += r0.w;
            v[4] += r1.x; v[5] += r1.y; v[6] += r1.z; v[7] += r1.w;
        }
        *(float4*)&out[o]     = make_float4(v[0], v[1], v[2], v[3]);
        *(float4*)&out[o + 4] = make_float4(v[4], v[5], v[6], v[7]);
    }
}

// ---------------------------------------------------------------------------
// Attention core v2: one block per (window, head). qkv layout [tok][kqv][h][32].
// Q,K staged transposed [32][68]; scores 64x64 GEMM with 4x4 register tiles;
// softmax writes P transposed; PV GEMM with 2x4 tiles. Scale folded into Q.
// ---------------------------------------------------------------------------
#define AST 68
#define ATTN_SMEM_FLOATS (2*32*AST + 49*32 + 64*AST + 49*AST)
#define ATTN_SMEM_BYTES  (ATTN_SMEM_FLOATS*4)

__global__ __launch_bounds__(256) void attn_core(
    const float* __restrict__ qkv, float* __restrict__ aout)
{
    extern __shared__ float sm[];
    float* s_qt = sm;                 // [32][68]  qT (scaled)
    float* s_kt = s_qt + 32*AST;      // [32][68]  kT
    float* s_v  = s_kt + 32*AST;      // [49][32]
    float* s_p  = s_v  + 49*32;       // [64][68]  scores (i-major)
    float* s_pT = s_p  + 64*AST;      // [49][68]  probs (j-major)

    int widx = blockIdx.x;
    int head = blockIdx.y;
    int b  = widx >> 6;
    int wi = (widx >> 3) & 7;
    int wj = widx & 7;
    int tid  = threadIdx.x;
    int warp = tid >> 5, lane = tid & 31;
    const float scale = 0.17677669529663687f;  // 32^-0.5

    // ---- load q (scaled, transposed), k (transposed), v ----
    for (int idx = tid; idx < 49*8; idx += 256) {
        int n = idx >> 3, d4 = (idx & 7) << 2;
        int h  = (n/7)*8 + wi;
        int w2 = (n%7)*8 + wj;
        const float* bp = qkv + ((size_t)((b*HH + h)*WW) + w2)*576 + head*32 + d4;
        float4 qv = *(const float4*)bp;
        float4 kv = *(const float4*)(bp + 192);
        float4 vv = *(const float4*)(bp + 384);
        s_qt[(d4+0)*AST + n] = qv.x*scale;
        s_qt[(d4+1)*AST + n] = qv.y*scale;
        s_qt[(d4+2)*AST + n] = qv.z*scale;
        s_qt[(d4+3)*AST + n] = qv.w*scale;
        s_kt[(d4+0)*AST + n] = kv.x;
        s_kt[(d4+1)*AST + n] = kv.y;
        s_kt[(d4+2)*AST + n] = kv.z;
        s_kt[(d4+3)*AST + n] = kv.w;
        *(float4*)&s_v[n*32 + d4] = vv;
    }
    // zero-pad qT/kT cols 49..63 and pT cols 49..63
    for (int idx = tid; idx < 32*15; idx += 256) {
        int d = idx/15, c = 49 + idx%15;
        s_qt[d*AST + c] = 0.f;
        s_kt[d*AST + c] = 0.f;
    }
    for (int idx = tid; idx < 49*15; idx += 256) {
        int j = idx/15, c = 49 + idx%15;
        s_pT[j*AST + c] = 0.f;
    }
    __syncthreads();

    // ---- scores: S[64][64] = qT^T @ kT, 16x16 threads, 4x4 tiles ----
    {
        int tx = tid & 15, ty = tid >> 4;
        float2 acc[4][2];
#pragma unroll
        for (int i = 0; i < 4; i++) { acc[i][0] = make_float2(0,0); acc[i][1] = make_float2(0,0); }
#pragma unroll 4
        for (int d = 0; d < 32; d++) {
            float4 a4 = *(const float4*)&s_qt[d*AST + ty*4];
            float4 b4 = *(const float4*)&s_kt[d*AST + tx*4];
            float2 b01 = make_float2(b4.x, b4.y);
            float2 b23 = make_float2(b4.z, b4.w);
            float ar[4] = {a4.x, a4.y, a4.z, a4.w};
#pragma unroll
            for (int i = 0; i < 4; i++) {
                float2 a2 = make_float2(ar[i], ar[i]);
                ffma2(acc[i][0], a2, b01);
                ffma2(acc[i][1], a2, b23);
            }
        }
#pragma unroll
        for (int i = 0; i < 4; i++) {
            *(float4*)&s_p[(ty*4 + i)*AST + tx*4] =
                make_float4(acc[i][0].x, acc[i][0].y, acc[i][1].x, acc[i][1].y);
        }
    }
    __syncthreads();

    // ---- softmax rows, write transposed ----
    for (int i = warp; i < NTOK; i += 8) {
        const float* row = &s_p[i*AST];
        float v1 = row[lane];
        bool has2 = (lane + 32) < NTOK;
        float v2 = has2 ? row[lane + 32] : -INFINITY;
        float mx = fmaxf(v1, v2);
#pragma unroll
        for (int o = 16; o; o >>= 1) mx = fmaxf(mx, __shfl_xor_sync(0xffffffffu, mx, o));
        float e1 = expf(v1 - mx);
        float e2 = has2 ? expf(v2 - mx) : 0.f;
        float ss = e1 + e2;
#pragma unroll
        for (int o = 16; o; o >>= 1) ss += __shfl_xor_sync(0xffffffffu, ss, o);
        float inv = 1.f / ss;
        s_pT[lane*AST + i] = e1 * inv;
        if (has2) s_pT[(lane+32)*AST + i] = e2 * inv;
    }
    __syncthreads();

    // ---- PV: out[64][32] = pT^T @ v, 32x8 threads, 2x4 tiles ----
    {
        int ti = tid >> 3, td = tid & 7;
        float2 acc[2][2];
        acc[0][0] = make_float2(0,0); acc[0][1] = make_float2(0,0);
        acc[1][0] = make_float2(0,0); acc[1][1] = make_float2(0,0);
#pragma unroll 7
        for (int j = 0; j < NTOK; j++) {
            float2 a = *(const float2*)&s_pT[j*AST + ti*2];
            float4 b4 = *(const float4*)&s_v[j*32 + td*4];
            float2 b01 = make_float2(b4.x, b4.y);
            float2 b23 = make_float2(b4.z, b4.w);
            float2 ax = make_float2(a.x, a.x);
            float2 ay = make_float2(a.y, a.y);
            ffma2(acc[0][0], ax, b01); ffma2(acc[0][1], ax, b23);
            ffma2(acc[1][0], ay, b01); ffma2(acc[1][1], ay, b23);
        }
#pragma unroll
        for (int r = 0; r < 2; r++) {
            int i = ti*2 + r;
            if (i < NTOK) {
                int h  = (i/7)*8 + wi;
                int w2 = (i%7)*8 + wj;
                *(float4*)&aout[((size_t)((b*HH + h)*WW) + w2)*CC + head*HDIM + td*4] =
                    make_float4(acc[r][0].x, acc[r][0].y, acc[r][1].x, acc[r][1].y);
            }
        }
    }
}

// ---------------------------------------------------------------------------
extern "C" void kernel_launch(void* const* d_in, const int* in_sizes, int n_in,
                              void* d_out, int out_size)
{
    int p = 0;
    const float* x = (const float*)d_in[p++];
    while (p < n_in && in_sizes[p] == 1) p++;   // skip scalar H, W if present
    const float* cpe0_w = (const float*)d_in[p++];
    const float* cpe0_b = (const float*)d_in[p++];
    const float* cpe1_w = (const float*)d_in[p++];
    const float* cpe1_b = (const float*)d_in[p++];
    const float* n1_g   = (const float*)d_in[p++];
    const float* n1_b   = (const float*)d_in[p++];
    const float* qkv_w  = (const float*)d_in[p++];
    const float* qkv_b  = (const float*)d_in[p++];
    const float* proj_w = (const float*)d_in[p++];
    const float* proj_b = (const float*)d_in[p++];
    const float* n2_g   = (const float*)d_in[p++];
    const float* n2_b   = (const float*)d_in[p++];
    const float* fc1_w  = (const float*)d_in[p++];
    const float* fc1_b  = (const float*)d_in[p++];
    const float* fc2_w  = (const float*)d_in[p++];
    const float* fc2_b  = (const float*)d_in[p++];

    float *b0, *b1, *b2, *xn, *attn, *qkv, *hbuf, *wp, *bp;
    cudaGetSymbolAddress((void**)&b0, g_buf0);
    cudaGetSymbolAddress((void**)&b1, g_buf1);
    cudaGetSymbolAddress((void**)&b2, g_buf2);
    cudaGetSymbolAddress((void**)&xn, g_xn);
    cudaGetSymbolAddress((void**)&attn, g_attn);
    cudaGetSymbolAddress((void**)&qkv, g_qkv);
    cudaGetSymbolAddress((void**)&hbuf, g_h);
    cudaGetSymbolAddress((void**)&wp, g_wp);
    cudaGetSymbolAddress((void**)&bp, g_bp);

    cudaFuncSetAttribute(gemm_kernel<192,false,false>,
                         cudaFuncAttributeMaxDynamicSharedMemorySize, GEMM_SMEM_BYTES);
    cudaFuncSetAttribute(gemm_kernel<192,false,true>,
                         cudaFuncAttributeMaxDynamicSharedMemorySize, GEMM_SMEM_BYTES);
    cudaFuncSetAttribute(gemm_kernel<192,true,false>,
                         cudaFuncAttributeMaxDynamicSharedMemorySize, GEMM_SMEM_BYTES);
    cudaFuncSetAttribute(gemm_kernel<768,false,true>,
                         cudaFuncAttributeMaxDynamicSharedMemorySize, GEMM_SMEM_BYTES);
    cudaFuncSetAttribute(attn_core,
                         cudaFuncAttributeMaxDynamicSharedMemorySize, ATTN_SMEM_BYTES);

    dim3 gcpe(HH, BATCH);
    const int MB = TOKENS/128;   // 784 row blocks

    permute_qkv_w<<<(192*576)/256, 256>>>(qkv_w, qkv_b, wp, bp);
    cpe_kernel<<<gcpe, CC>>>(x, cpe0_w, cpe0_b, b0);
    ln_kernel<<<TOKENS/8, 256>>>(b0, n1_g, n1_b, xn);
    gemm_kernel<192,false,false><<<dim3(MB,3), 384, GEMM_SMEM_BYTES>>>(
        xn, wp, bp, nullptr, qkv, 576);
    attn_core<<<dim3(BATCH*64, NHEAD), 256, ATTN_SMEM_BYTES>>>(qkv, attn);
    gemm_kernel<192,false,true><<<dim3(MB,1), 384, GEMM_SMEM_BYTES>>>(
        attn, proj_w, proj_b, b0, b1, 192);
    cpe_kernel<<<gcpe, CC>>>(b1, cpe1_w, cpe1_b, b2);
    ln_kernel<<<TOKENS/8, 256>>>(b2, n2_g, n2_b, xn);
    gemm_kernel<192,true,false><<<dim3(MB,4), 384, GEMM_SMEM_BYTES>>>(
        xn, fc1_w, fc1_b, nullptr, hbuf, 768);
    gemm_kernel<768,false,true><<<dim3(MB,1), 384, GEMM_SMEM_BYTES>>>(
        hbuf, fc2_w, fc2_b, b2, (float*)d_out, 192);
}

// round 5
// speedup vs baseline: 3.4353x; 1.4443x over previous
#include <cuda_runtime.h>
#include <math.h>

#define BATCH 32
#define HH 56
#define WW 56
#define CC 192
#define NHEAD 6
#define HDIM 32
#define NTOK 49
#define HIDDEN 768
#define TOKENS (BATCH*HH*WW)   // 100352

// Scratch (device globals — no runtime allocation allowed)
__device__ float g_buf0[TOKENS*CC];      // shortcut (after cpe0)
__device__ float g_buf1[TOKENS*CC];      // y (after attn residual)
__device__ float g_buf2[TOKENS*CC];      // y2 (after cpe1)
__device__ float g_xn  [TOKENS*CC];      // LN output (reused)
__device__ float g_attn[TOKENS*CC];      // attention output (pre-proj)
__device__ float g_qkv [TOKENS*3*CC];    // qkv in [tok][kqv][head][32] layout
__device__ float g_h   [TOKENS*HIDDEN];  // mlp hidden
__device__ float g_wp  [CC*3*CC];        // permuted qkv weight
__device__ float g_bp  [3*CC];           // permuted qkv bias

__device__ __forceinline__ float gelu_exact(float x) {
    return 0.5f * x * (1.f + erff(x * 0.7071067811865475f));
}

// Packed dual-fp32 FMA
__device__ __forceinline__ void ffma2(float2& d, float2 a, float2 b) {
    asm("fma.rn.f32x2 %0, %1, %2, %0;"
        : "+l"(reinterpret_cast<unsigned long long&>(d))
        : "l"(reinterpret_cast<unsigned long long&>(a)),
          "l"(reinterpret_cast<unsigned long long&>(b)));
}

// cp.async helpers
__device__ __forceinline__ void cp_async16(float* smem, const float* gmem) {
    unsigned s = (unsigned)__cvta_generic_to_shared(smem);
    asm volatile("cp.async.cg.shared.global [%0], [%1], 16;" :: "r"(s), "l"(gmem));
}
__device__ __forceinline__ void cp_commit() {
    asm volatile("cp.async.commit_group;");
}
template<int N> __device__ __forceinline__ void cp_wait() {
    asm volatile("cp.async.wait_group %0;" :: "n"(N));
}

// ---------------------------------------------------------------------------
// One-shot permutation of qkv weight/bias columns:
// dst col = kk*192 + h*32 + d  <-  src col = d*18 + kk*6 + h  (faithful (d k h))
// ---------------------------------------------------------------------------
__global__ void permute_qkv_w(const float* __restrict__ W,
                              const float* __restrict__ bias,
                              float* __restrict__ Wp, float* __restrict__ bp)
{
    int idx = blockIdx.x*256 + threadIdx.x;   // grid covers 192*576
    int dst = idx % 576, k = idx / 576;
    int kk = dst / 192, rem = dst % 192;
    int h = rem / 32, d = rem % 32;
    int src = d*18 + kk*6 + h;
    Wp[idx] = W[k*576 + src];
    if (idx < 576) bp[idx] = bias[src];
}

// ---------------------------------------------------------------------------
// Depthwise 3x3 conv (SAME) + residual
// ---------------------------------------------------------------------------
__global__ void cpe_kernel(const float* __restrict__ in,
                           const float* __restrict__ wgt,
                           const float* __restrict__ bias,
                           float* __restrict__ out)
{
    int h = blockIdx.x;
    int b = blockIdx.y;
    int c = threadIdx.x;
    float kw[9];
#pragma unroll
    for (int i = 0; i < 9; i++) kw[i] = wgt[c*9 + i];
    float bb = bias[c];
    const float* base  = in  + ((size_t)b*HH*WW)*CC + c;
    float*       obase = out + ((size_t)b*HH*WW)*CC + c;

    float colL[3], colM[3], colR[3];
#pragma unroll
    for (int dy = 0; dy < 3; dy++) {
        colL[dy] = 0.f;
        int hy = h + dy - 1;
        colM[dy] = (hy >= 0 && hy < HH) ? base[(size_t)(hy*WW)*CC] : 0.f;
    }
    for (int x = 0; x < WW; x++) {
#pragma unroll
        for (int dy = 0; dy < 3; dy++) {
            int hy = h + dy - 1;
            colR[dy] = (x+1 < WW && hy >= 0 && hy < HH)
                       ? base[(size_t)(hy*WW + x + 1)*CC] : 0.f;
        }
        float acc = bb;
#pragma unroll
        for (int dy = 0; dy < 3; dy++) {
            acc = fmaf(kw[dy*3+0], colL[dy], acc);
            acc = fmaf(kw[dy*3+1], colM[dy], acc);
            acc = fmaf(kw[dy*3+2], colR[dy], acc);
        }
        obase[(size_t)(h*WW + x)*CC] = colM[1] + acc;
#pragma unroll
        for (int dy = 0; dy < 3; dy++) { colL[dy] = colM[dy]; colM[dy] = colR[dy]; }
    }
}

// ---------------------------------------------------------------------------
// Per-token LayerNorm: one warp per token
// ---------------------------------------------------------------------------
__global__ void ln_kernel(const float* __restrict__ in,
                          const float* __restrict__ g, const float* __restrict__ b,
                          float* __restrict__ out)
{
    int tok  = blockIdx.x*8 + (threadIdx.x >> 5);
    int lane = threadIdx.x & 31;
    const float* p = in  + (size_t)tok*CC;
    float*       o = out + (size_t)tok*CC;
    float vals[6]; float s = 0.f;
#pragma unroll
    for (int u = 0; u < 6; u++) { vals[u] = p[lane + u*32]; s += vals[u]; }
#pragma unroll
    for (int off = 16; off; off >>= 1) s += __shfl_xor_sync(0xffffffffu, s, off);
    float m = s * (1.f/192.f);
    float vv = 0.f;
#pragma unroll
    for (int u = 0; u < 6; u++) { float d = vals[u]-m; vv += d*d; }
#pragma unroll
    for (int off = 16; off; off >>= 1) vv += __shfl_xor_sync(0xffffffffu, vv, off);
    float rs = rsqrtf(vv*(1.f/192.f) + 1e-5f);
#pragma unroll
    for (int u = 0; u < 6; u++) {
        int c = lane + u*32;
        o[c] = (vals[u]-m)*rs*g[c] + b[c];
    }
}

// ---------------------------------------------------------------------------
// GEMM v2: out[M,N] = A[M,KTOT] @ W[KTOT,N] + bias (+gelu) (+residual)
// 128x192 block tile, 384 threads, 8 rows x (4+4) cols per thread.
// cp.async 2-stage double buffer; A row-major in smem (broadcast LDS.128);
// thread cols split {cg*4, 96+cg*4} for 3-phase W reads.
// ---------------------------------------------------------------------------
#define ASZ 8192     // 128*64 floats per stage
#define WSZ 12288    // 64*192 floats per stage
#define GEMM_SMEM_BYTES ((2*ASZ + 2*WSZ)*4)

__device__ __forceinline__ void gemm_stage(
    float* sA, float* sW, const float* A, const float* W,
    int row0, int col0, int k0, int KTOT, int N, int tid)
{
    for (int idx = tid; idx < 2048; idx += 384) {
        int r = idx >> 4, q = (idx & 15) << 2;
        cp_async16(sA + r*64 + q, A + (size_t)(row0 + r)*KTOT + k0 + q);
    }
#pragma unroll
    for (int i = 0; i < 8; i++) {
        int idx = tid + i*384;
        int k = idx / 48, q = (idx % 48) << 2;
        cp_async16(sW + k*192 + q, W + (size_t)(k0 + k)*N + col0 + q);
    }
}

template<int KTOT, bool GELU, bool RES>
__global__ __launch_bounds__(384) void gemm_kernel(
    const float* __restrict__ A, const float* __restrict__ W,
    const float* __restrict__ bias, const float* __restrict__ res,
    float* __restrict__ out, int N)
{
    extern __shared__ float sm[];
    float* sA = sm;             // 2 stages of [128][64]
    float* sW = sm + 2*ASZ;     // 2 stages of [64][192]

    const int NCH = KTOT/64;
    int tid = threadIdx.x;
    int rg = tid / 24;          // 0..15, rows rg*8..rg*8+7
    int cg = tid % 24;          // cols cg*4..+3 and 96+cg*4..+3
    int row0 = blockIdx.x * 128;
    int col0 = blockIdx.y * 192;

    float2 acc[8][4];
#pragma unroll
    for (int i = 0; i < 8; i++)
#pragma unroll
        for (int j = 0; j < 4; j++) acc[i][j] = make_float2(0.f, 0.f);

    // prologue: prefetch chunks 0 and 1
    gemm_stage(sA, sW, A, W, row0, col0, 0, KTOT, N, tid);
    cp_commit();
    gemm_stage(sA + ASZ, sW + WSZ, A, W, row0, col0, 64, KTOT, N, tid);
    cp_commit();

    for (int c = 0; c < NCH; c++) {
        if (c < NCH-1) cp_wait<1>(); else cp_wait<0>();
        __syncthreads();
        const float* cA = sA + (c & 1)*ASZ;
        const float* cW = sW + (c & 1)*WSZ;

#pragma unroll 4
        for (int k4 = 0; k4 < 16; k4++) {
            float4 aq[8];
#pragma unroll
            for (int i = 0; i < 8; i++)
                aq[i] = *(const float4*)&cA[(rg*8 + i)*64 + k4*4];
#pragma unroll
            for (int kk = 0; kk < 4; kk++) {
                const float* wrow = &cW[(k4*4 + kk)*192];
                float4 w0 = *(const float4*)&wrow[cg*4];
                float4 w1 = *(const float4*)&wrow[96 + cg*4];
                float2 b0 = make_float2(w0.x, w0.y);
                float2 b1 = make_float2(w0.z, w0.w);
                float2 b2 = make_float2(w1.x, w1.y);
                float2 b3 = make_float2(w1.z, w1.w);
#pragma unroll
                for (int i = 0; i < 8; i++) {
                    float a = ((const float*)&aq[i])[kk];
                    float2 a2 = make_float2(a, a);
                    ffma2(acc[i][0], a2, b0);
                    ffma2(acc[i][1], a2, b1);
                    ffma2(acc[i][2], a2, b2);
                    ffma2(acc[i][3], a2, b3);
                }
            }
        }
        __syncthreads();
        if (c + 2 < NCH) {
            gemm_stage(sA + (c & 1)*ASZ, sW + (c & 1)*WSZ,
                       A, W, row0, col0, (c + 2)*64, KTOT, N, tid);
            cp_commit();
        }
    }

    // epilogue
    float4 bias0 = *(const float4*)&bias[col0 + cg*4];
    float4 bias1 = *(const float4*)&bias[col0 + 96 + cg*4];
#pragma unroll
    for (int i = 0; i < 8; i++) {
        size_t row = (size_t)(row0 + rg*8 + i);
        size_t o0 = row*N + col0 + cg*4;
        size_t o1 = row*N + col0 + 96 + cg*4;
        float v[8];
        v[0] = acc[i][0].x + bias0.x; v[1] = acc[i][0].y + bias0.y;
        v[2] = acc[i][1].x + bias0.z; v[3] = acc[i][1].y + bias0.w;
        v[4] = acc[i][2].x + bias1.x; v[5] = acc[i][2].y + bias1.y;
        v[6] = acc[i][3].x + bias1.z; v[7] = acc[i][3].y + bias1.w;
        if (GELU) {
#pragma unroll
            for (int j = 0; j < 8; j++) v[j] = gelu_exact(v[j]);
        }
        if (RES) {
            float4 r0 = *(const float4*)&res[o0];
            float4 r1 = *(const float4*)&res[o1];
            v[0] += r0.x; v[1] += r0.y; v[2] += r0.z; v[3] += r0.w;
            v[4] += r1.x; v[5] += r1.y; v[6] += r1.z; v[7] += r1.w;
        }
        *(float4*)&out[o0] = make_float4(v[0], v[1], v[2], v[3]);
        *(float4*)&out[o1] = make_float4(v[4], v[5], v[6], v[7]);
    }
}

// ---------------------------------------------------------------------------
// Attention core: one block per (window, head). qkv layout [tok][kqv][h][32].
// ---------------------------------------------------------------------------
#define AST 68
#define ATTN_SMEM_FLOATS (2*32*AST + 49*32 + 64*AST + 49*AST)
#define ATTN_SMEM_BYTES  (ATTN_SMEM_FLOATS*4)

__global__ __launch_bounds__(256) void attn_core(
    const float* __restrict__ qkv, float* __restrict__ aout)
{
    extern __shared__ float sm[];
    float* s_qt = sm;                 // [32][68]  qT (scaled)
    float* s_kt = s_qt + 32*AST;      // [32][68]  kT
    float* s_v  = s_kt + 32*AST;      // [49][32]
    float* s_p  = s_v  + 49*32;       // [64][68]  scores (i-major)
    float* s_pT = s_p  + 64*AST;      // [49][68]  probs (j-major)

    int widx = blockIdx.x;
    int head = blockIdx.y;
    int b  = widx >> 6;
    int wi = (widx >> 3) & 7;
    int wj = widx & 7;
    int tid  = threadIdx.x;
    int warp = tid >> 5, lane = tid & 31;
    const float scale = 0.17677669529663687f;  // 32^-0.5

    for (int idx = tid; idx < 49*8; idx += 256) {
        int n = idx >> 3, d4 = (idx & 7) << 2;
        int h  = (n/7)*8 + wi;
        int w2 = (n%7)*8 + wj;
        const float* bp = qkv + ((size_t)((b*HH + h)*WW) + w2)*576 + head*32 + d4;
        float4 qv = *(const float4*)bp;
        float4 kv = *(const float4*)(bp + 192);
        float4 vv = *(const float4*)(bp + 384);
        s_qt[(d4+0)*AST + n] = qv.x*scale;
        s_qt[(d4+1)*AST + n] = qv.y*scale;
        s_qt[(d4+2)*AST + n] = qv.z*scale;
        s_qt[(d4+3)*AST + n] = qv.w*scale;
        s_kt[(d4+0)*AST + n] = kv.x;
        s_kt[(d4+1)*AST + n] = kv.y;
        s_kt[(d4+2)*AST + n] = kv.z;
        s_kt[(d4+3)*AST + n] = kv.w;
        *(float4*)&s_v[n*32 + d4] = vv;
    }
    for (int idx = tid; idx < 32*15; idx += 256) {
        int d = idx/15, c = 49 + idx%15;
        s_qt[d*AST + c] = 0.f;
        s_kt[d*AST + c] = 0.f;
    }
    for (int idx = tid; idx < 49*15; idx += 256) {
        int j = idx/15, c = 49 + idx%15;
        s_pT[j*AST + c] = 0.f;
    }
    __syncthreads();

    {
        int tx = tid & 15, ty = tid >> 4;
        float2 acc[4][2];
#pragma unroll
        for (int i = 0; i < 4; i++) { acc[i][0] = make_float2(0,0); acc[i][1] = make_float2(0,0); }
#pragma unroll 4
        for (int d = 0; d < 32; d++) {
            float4 a4 = *(const float4*)&s_qt[d*AST + ty*4];
            float4 b4 = *(const float4*)&s_kt[d*AST + tx*4];
            float2 b01 = make_float2(b4.x, b4.y);
            float2 b23 = make_float2(b4.z, b4.w);
            float ar[4] = {a4.x, a4.y, a4.z, a4.w};
#pragma unroll
            for (int i = 0; i < 4; i++) {
                float2 a2 = make_float2(ar[i], ar[i]);
                ffma2(acc[i][0], a2, b01);
                ffma2(acc[i][1], a2, b23);
            }
        }
#pragma unroll
        for (int i = 0; i < 4; i++) {
            *(float4*)&s_p[(ty*4 + i)*AST + tx*4] =
                make_float4(acc[i][0].x, acc[i][0].y, acc[i][1].x, acc[i][1].y);
        }
    }
    __syncthreads();

    for (int i = warp; i < NTOK; i += 8) {
        const float* row = &s_p[i*AST];
        float v1 = row[lane];
        bool has2 = (lane + 32) < NTOK;
        float v2 = has2 ? row[lane + 32] : -INFINITY;
        float mx = fmaxf(v1, v2);
#pragma unroll
        for (int o = 16; o; o >>= 1) mx = fmaxf(mx, __shfl_xor_sync(0xffffffffu, mx, o));
        float e1 = expf(v1 - mx);
        float e2 = has2 ? expf(v2 - mx) : 0.f;
        float ss = e1 + e2;
#pragma unroll
        for (int o = 16; o; o >>= 1) ss += __shfl_xor_sync(0xffffffffu, ss, o);
        float inv = 1.f / ss;
        s_pT[lane*AST + i] = e1 * inv;
        if (has2) s_pT[(lane+32)*AST + i] = e2 * inv;
    }
    __syncthreads();

    {
        int ti = tid >> 3, td = tid & 7;
        float2 acc[2][2];
        acc[0][0] = make_float2(0,0); acc[0][1] = make_float2(0,0);
        acc[1][0] = make_float2(0,0); acc[1][1] = make_float2(0,0);
#pragma unroll 7
        for (int j = 0; j < NTOK; j++) {
            float2 a = *(const float2*)&s_pT[j*AST + ti*2];
            float4 b4 = *(const float4*)&s_v[j*32 + td*4];
            float2 b01 = make_float2(b4.x, b4.y);
            float2 b23 = make_float2(b4.z, b4.w);
            float2 ax = make_float2(a.x, a.x);
            float2 ay = make_float2(a.y, a.y);
            ffma2(acc[0][0], ax, b01); ffma2(acc[0][1], ax, b23);
            ffma2(acc[1][0], ay, b01); ffma2(acc[1][1], ay, b23);
        }
#pragma unroll
        for (int r = 0; r < 2; r++) {
            int i = ti*2 + r;
            if (i < NTOK) {
                int h  = (i/7)*8 + wi;
                int w2 = (i%7)*8 + wj;
                *(float4*)&aout[((size_t)((b*HH + h)*WW) + w2)*CC + head*HDIM + td*4] =
                    make_float4(acc[r][0].x, acc[r][0].y, acc[r][1].x, acc[r][1].y);
            }
        }
    }
}

// ---------------------------------------------------------------------------
extern "C" void kernel_launch(void* const* d_in, const int* in_sizes, int n_in,
                              void* d_out, int out_size)
{
    int p = 0;
    const float* x = (const float*)d_in[p++];
    while (p < n_in && in_sizes[p] == 1) p++;   // skip scalar H, W if present
    const float* cpe0_w = (const float*)d_in[p++];
    const float* cpe0_b = (const float*)d_in[p++];
    const float* cpe1_w = (const float*)d_in[p++];
    const float* cpe1_b = (const float*)d_in[p++];
    const float* n1_g   = (const float*)d_in[p++];
    const float* n1_b   = (const float*)d_in[p++];
    const float* qkv_w  = (const float*)d_in[p++];
    const float* qkv_b  = (const float*)d_in[p++];
    const float* proj_w = (const float*)d_in[p++];
    const float* proj_b = (const float*)d_in[p++];
    const float* n2_g   = (const float*)d_in[p++];
    const float* n2_b   = (const float*)d_in[p++];
    const float* fc1_w  = (const float*)d_in[p++];
    const float* fc1_b  = (const float*)d_in[p++];
    const float* fc2_w  = (const float*)d_in[p++];
    const float* fc2_b  = (const float*)d_in[p++];

    float *b0, *b1, *b2, *xn, *attn, *qkv, *hbuf, *wp, *bp;
    cudaGetSymbolAddress((void**)&b0, g_buf0);
    cudaGetSymbolAddress((void**)&b1, g_buf1);
    cudaGetSymbolAddress((void**)&b2, g_buf2);
    cudaGetSymbolAddress((void**)&xn, g_xn);
    cudaGetSymbolAddress((void**)&attn, g_attn);
    cudaGetSymbolAddress((void**)&qkv, g_qkv);
    cudaGetSymbolAddress((void**)&hbuf, g_h);
    cudaGetSymbolAddress((void**)&wp, g_wp);
    cudaGetSymbolAddress((void**)&bp, g_bp);

    cudaFuncSetAttribute(gemm_kernel<192,false,false>,
                         cudaFuncAttributeMaxDynamicSharedMemorySize, GEMM_SMEM_BYTES);
    cudaFuncSetAttribute(gemm_kernel<192,false,true>,
                         cudaFuncAttributeMaxDynamicSharedMemorySize, GEMM_SMEM_BYTES);
    cudaFuncSetAttribute(gemm_kernel<192,true,false>,
                         cudaFuncAttributeMaxDynamicSharedMemorySize, GEMM_SMEM_BYTES);
    cudaFuncSetAttribute(gemm_kernel<768,false,true>,
                         cudaFuncAttributeMaxDynamicSharedMemorySize, GEMM_SMEM_BYTES);
    cudaFuncSetAttribute(attn_core,
                         cudaFuncAttributeMaxDynamicSharedMemorySize, ATTN_SMEM_BYTES);

    dim3 gcpe(HH, BATCH);
    const int MB = TOKENS/128;   // 784 row blocks

    permute_qkv_w<<<(192*576)/256, 256>>>(qkv_w, qkv_b, wp, bp);
    cpe_kernel<<<gcpe, CC>>>(x, cpe0_w, cpe0_b, b0);
    ln_kernel<<<TOKENS/8, 256>>>(b0, n1_g, n1_b, xn);
    gemm_kernel<192,false,false><<<dim3(MB,3), 384, GEMM_SMEM_BYTES>>>(
        xn, wp, bp, nullptr, qkv, 576);
    attn_core<<<dim3(BATCH*64, NHEAD), 256, ATTN_SMEM_BYTES>>>(qkv, attn);
    gemm_kernel<192,false,true><<<dim3(MB,1), 384, GEMM_SMEM_BYTES>>>(
        attn, proj_w, proj_b, b0, b1, 192);
    cpe_kernel<<<gcpe, CC>>>(b1, cpe1_w, cpe1_b, b2);
    ln_kernel<<<TOKENS/8, 256>>>(b2, n2_g, n2_b, xn);
    gemm_kernel<192,true,false><<<dim3(MB,4), 384, GEMM_SMEM_BYTES>>>(
        xn, fc1_w, fc1_b, nullptr, hbuf, 768);
    gemm_kernel<768,false,true><<<dim3(MB,1), 384, GEMM_SMEM_BYTES>>>(
        hbuf, fc2_w, fc2_b, b2, (float*)d_out, 192);
}

// round 7
// speedup vs baseline: 5.4824x; 1.5959x over previous
#include <cuda_runtime.h>
#include <math.h>
#include <stdint.h>

#define BATCH 32
#define HH 56
#define WW 56
#define CC 192
#define NHEAD 6
#define HDIM 32
#define NTOK 49
#define HIDDEN 768
#define TOKENS (BATCH*HH*WW)   // 100352

// Scratch (device globals — no runtime allocation allowed)
__device__ float g_buf0[TOKENS*CC];      // shortcut (after cpe0)
__device__ float g_buf1[TOKENS*CC];      // y (after attn residual)
__device__ float g_buf2[TOKENS*CC];      // y2 (after cpe1)
__device__ float g_xn  [TOKENS*CC];      // LN output (tf32-rounded)
__device__ float g_attn[TOKENS*CC];      // attention output (tf32-rounded)
__device__ float g_qkv [TOKENS*3*CC];    // qkv in [tok][kqv][head][32] layout
__device__ float g_h   [TOKENS*HIDDEN];  // mlp hidden (tf32-rounded)
__device__ float g_wqkv[576*192];        // transposed+permuted qkv weight [N][K]
__device__ float g_bqkv[576];            // permuted qkv bias
__device__ float g_wproj[192*192];       // [N][K]
__device__ float g_wfc1[768*192];        // [N][K]
__device__ float g_wfc2[192*768];        // [N][K]

__device__ __forceinline__ float gelu_exact(float x) {
    return 0.5f * x * (1.f + erff(x * 0.7071067811865475f));
}
__device__ __forceinline__ float to_tf32(float x) {
    unsigned u;
    asm("cvt.rna.tf32.f32 %0, %1;" : "=r"(u) : "f"(x));
    return __uint_as_float(u);
}
// Packed dual-fp32 FMA (attention core)
__device__ __forceinline__ void ffma2(float2& d, float2 a, float2 b) {
    asm("fma.rn.f32x2 %0, %1, %2, %0;"
        : "+l"(reinterpret_cast<unsigned long long&>(d))
        : "l"(reinterpret_cast<unsigned long long&>(a)),
          "l"(reinterpret_cast<unsigned long long&>(b)));
}
// cp.async helpers
__device__ __forceinline__ void cp_async16(void* smem, const void* gmem) {
    unsigned s = (unsigned)__cvta_generic_to_shared(smem);
    asm volatile("cp.async.cg.shared.global [%0], [%1], 16;" :: "r"(s), "l"(gmem));
}
__device__ __forceinline__ void cp_commit() {
    asm volatile("cp.async.commit_group;");
}
template<int N> __device__ __forceinline__ void cp_wait() {
    asm volatile("cp.async.wait_group %0;" :: "n"(N));
}
// tf32 tensor-core mma (sm_80+ HMMA path; compiles at compute_103)
__device__ __forceinline__ void mma_tf32(float* c, const uint32_t* a,
                                         uint32_t b0, uint32_t b1) {
    asm volatile(
        "mma.sync.aligned.m16n8k8.row.col.f32.tf32.tf32.f32 "
        "{%0,%1,%2,%3}, {%4,%5,%6,%7}, {%8,%9}, {%0,%1,%2,%3};"
        : "+f"(c[0]), "+f"(c[1]), "+f"(c[2]), "+f"(c[3])
        : "r"(a[0]), "r"(a[1]), "r"(a[2]), "r"(a[3]), "r"(b0), "r"(b1));
}

// ---------------------------------------------------------------------------
// One-shot weight transposes (W[K][N] -> Wt[N][K], tf32-rounded)
// ---------------------------------------------------------------------------
__global__ void transpose_wt(const float* __restrict__ W, float* __restrict__ Wt,
                             int K, int N)
{
    int idx = blockIdx.x*256 + threadIdx.x;
    int n = idx / K, k = idx % K;
    Wt[idx] = to_tf32(W[(size_t)k*N + n]);
}
// qkv: dst row n = kk*192 + h*32 + d  <-  src col d*18 + kk*6 + h (faithful (d k h))
__global__ void permute_qkv_wt(const float* __restrict__ W,
                               const float* __restrict__ bias,
                               float* __restrict__ Wt, float* __restrict__ bq)
{
    int idx = blockIdx.x*256 + threadIdx.x;   // 576*192
    int n = idx / 192, k = idx % 192;
    int kk = n / 192;
    int rem = n % 192;
    int h = rem / 32, d = rem % 32;
    int src = d*18 + kk*6 + h;
    Wt[idx] = to_tf32(W[(size_t)k*576 + src]);
    if (k == 0) bq[n] = bias[src];
}

// ---------------------------------------------------------------------------
// Depthwise 3x3 conv (SAME) + residual
// ---------------------------------------------------------------------------
__global__ void cpe_kernel(const float* __restrict__ in,
                           const float* __restrict__ wgt,
                           const float* __restrict__ bias,
                           float* __restrict__ out)
{
    int h = blockIdx.x;
    int b = blockIdx.y;
    int c = threadIdx.x;
    float kw[9];
#pragma unroll
    for (int i = 0; i < 9; i++) kw[i] = wgt[c*9 + i];
    float bb = bias[c];
    const float* base  = in  + ((size_t)b*HH*WW)*CC + c;
    float*       obase = out + ((size_t)b*HH*WW)*CC + c;

    float colL[3], colM[3], colR[3];
#pragma unroll
    for (int dy = 0; dy < 3; dy++) {
        colL[dy] = 0.f;
        int hy = h + dy - 1;
        colM[dy] = (hy >= 0 && hy < HH) ? base[(size_t)(hy*WW)*CC] : 0.f;
    }
    for (int x = 0; x < WW; x++) {
#pragma unroll
        for (int dy = 0; dy < 3; dy++) {
            int hy = h + dy - 1;
            colR[dy] = (x+1 < WW && hy >= 0 && hy < HH)
                       ? base[(size_t)(hy*WW + x + 1)*CC] : 0.f;
        }
        float acc = bb;
#pragma unroll
        for (int dy = 0; dy < 3; dy++) {
            acc = fmaf(kw[dy*3+0], colL[dy], acc);
            acc = fmaf(kw[dy*3+1], colM[dy], acc);
            acc = fmaf(kw[dy*3+2], colR[dy], acc);
        }
        obase[(size_t)(h*WW + x)*CC] = colM[1] + acc;
#pragma unroll
        for (int dy = 0; dy < 3; dy++) { colL[dy] = colM[dy]; colM[dy] = colR[dy]; }
    }
}

// ---------------------------------------------------------------------------
// Per-token LayerNorm (tf32-rounded output; feeds GEMMs only)
// ---------------------------------------------------------------------------
__global__ void ln_kernel(const float* __restrict__ in,
                          const float* __restrict__ g, const float* __restrict__ b,
                          float* __restrict__ out)
{
    int tok  = blockIdx.x*8 + (threadIdx.x >> 5);
    int lane = threadIdx.x & 31;
    const float* p = in  + (size_t)tok*CC;
    float*       o = out + (size_t)tok*CC;
    float vals[6]; float s = 0.f;
#pragma unroll
    for (int u = 0; u < 6; u++) { vals[u] = p[lane + u*32]; s += vals[u]; }
#pragma unroll
    for (int off = 16; off; off >>= 1) s += __shfl_xor_sync(0xffffffffu, s, off);
    float m = s * (1.f/192.f);
    float vv = 0.f;
#pragma unroll
    for (int u = 0; u < 6; u++) { float d = vals[u]-m; vv += d*d; }
#pragma unroll
    for (int off = 16; off; off >>= 1) vv += __shfl_xor_sync(0xffffffffu, vv, off);
    float rs = rsqrtf(vv*(1.f/192.f) + 1e-5f);
#pragma unroll
    for (int u = 0; u < 6; u++) {
        int c = lane + u*32;
        o[c] = to_tf32((vals[u]-m)*rs*g[c] + b[c]);
    }
}

// ---------------------------------------------------------------------------
// tf32 mma.sync GEMM: out[M,N] = A[M,KTOT] @ Wt[N,KTOT]^T + bias (+gelu)(+res)
// 128x192 block tile, 256 threads (8 warps as 2x4), warp tile 64x48.
// K chunks of 32; cp.async double buffer; smem stride 36 (16B-aligned,
// conflict-free fragment loads: banks = (4r+k) mod 32 all distinct).
// ---------------------------------------------------------------------------
#define GA 4608            // 128*36 floats per A stage
#define GB 6912            // 192*36 floats per B stage
#define GEMM_SMEM_BYTES ((2*GA + 2*GB)*4)   // 92160

__device__ __forceinline__ void stage36(
    float* sA, float* sB, const float* A, const float* Wt,
    int row0, int col0, int k0, int KTOT, int tid)
{
#pragma unroll
    for (int i = 0; i < 4; i++) {                    // A: 128 rows x 8 quads
        int idx = tid + i*256;
        int r = idx >> 3, q = idx & 7;
        cp_async16(sA + r*36 + q*4, A + (size_t)(row0 + r)*KTOT + k0 + q*4);
    }
#pragma unroll
    for (int i = 0; i < 6; i++) {                    // B: 192 rows x 8 quads
        int idx = tid + i*256;
        int n = idx >> 3, q = idx & 7;
        cp_async16(sB + n*36 + q*4, Wt + (size_t)(col0 + n)*KTOT + k0 + q*4);
    }
}

template<int KTOT, bool GELU, bool RES>
__global__ __launch_bounds__(256) void gemm_mma(
    const float* __restrict__ A, const float* __restrict__ Wt,
    const float* __restrict__ bias, const float* __restrict__ res,
    float* __restrict__ out, int N)
{
    extern __shared__ float sm[];
    float* aS[2] = { sm,        sm + GA };
    float* bS[2] = { sm + 2*GA, sm + 2*GA + GB };

    const int NC = KTOT/32;
    int tid = threadIdx.x;
    int wid = tid >> 5, lane = tid & 31;
    int wm = wid >> 2, wn = wid & 3;           // warp grid 2x4
    int gid = lane >> 2, tig = lane & 3;
    int row0 = blockIdx.x * 128;
    int col0 = blockIdx.y * 192;

    float acc[4][6][4];
#pragma unroll
    for (int mi = 0; mi < 4; mi++)
#pragma unroll
        for (int ni = 0; ni < 6; ni++)
#pragma unroll
            for (int j = 0; j < 4; j++) acc[mi][ni][j] = 0.f;

    stage36(aS[0], bS[0], A, Wt, row0, col0, 0, KTOT, tid);
    cp_commit();
    stage36(aS[1], bS[1], A, Wt, row0, col0, 32, KTOT, tid);
    cp_commit();

    for (int c = 0; c < NC; c++) {
        if (c < NC-1) cp_wait<1>(); else cp_wait<0>();
        __syncthreads();
        const uint32_t* cA = (const uint32_t*)aS[c & 1] + (wm*64 + gid)*36 + tig;
        const uint32_t* cB = (const uint32_t*)bS[c & 1] + (wn*48 + gid)*36 + tig;
#pragma unroll
        for (int k8 = 0; k8 < 4; k8++) {
            uint32_t av[4][4];
#pragma unroll
            for (int mi = 0; mi < 4; mi++) {
                const uint32_t* p = cA + mi*16*36 + k8*8;
                av[mi][0] = p[0];
                av[mi][1] = p[8*36];
                av[mi][2] = p[4];
                av[mi][3] = p[8*36 + 4];
            }
#pragma unroll
            for (int ni = 0; ni < 6; ni++) {
                const uint32_t* p = cB + ni*8*36 + k8*8;
                uint32_t b0 = p[0], b1 = p[4];
#pragma unroll
                for (int mi = 0; mi < 4; mi++)
                    mma_tf32(acc[mi][ni], av[mi], b0, b1);
            }
        }
        __syncthreads();
        if (c + 2 < NC) {
            stage36(aS[c & 1], bS[c & 1], A, Wt, row0, col0, (c + 2)*32, KTOT, tid);
            cp_commit();
        }
    }

    // epilogue: c0,c1 -> (row, 2*tig..+1); c2,c3 -> (row+8, same cols)
#pragma unroll
    for (int mi = 0; mi < 4; mi++) {
        int r0 = row0 + wm*64 + mi*16 + gid;
#pragma unroll
        for (int ni = 0; ni < 6; ni++) {
            int col = col0 + wn*48 + ni*8 + 2*tig;
            float2 bb = *(const float2*)&bias[col];
            float v0x = acc[mi][ni][0] + bb.x, v0y = acc[mi][ni][1] + bb.y;
            float v1x = acc[mi][ni][2] + bb.x, v1y = acc[mi][ni][3] + bb.y;
            if (GELU) {
                v0x = to_tf32(gelu_exact(v0x)); v0y = to_tf32(gelu_exact(v0y));
                v1x = to_tf32(gelu_exact(v1x)); v1y = to_tf32(gelu_exact(v1y));
            }
            size_t o0 = (size_t)r0*N + col;
            size_t o1 = (size_t)(r0 + 8)*N + col;
            if (RES) {
                float2 r0v = *(const float2*)&res[o0];
                float2 r1v = *(const float2*)&res[o1];
                v0x += r0v.x; v0y += r0v.y;
                v1x += r1v.x; v1y += r1v.y;
            }
            *(float2*)&out[o0] = make_float2(v0x, v0y);
            *(float2*)&out[o1] = make_float2(v1x, v1y);
        }
    }
}

// ---------------------------------------------------------------------------
// Attention core: one block per (window, head). qkv layout [tok][kqv][h][32].
// ---------------------------------------------------------------------------
#define AST 68
#define ATTN_SMEM_FLOATS (2*32*AST + 49*32 + 64*AST + 49*AST)
#define ATTN_SMEM_BYTES  (ATTN_SMEM_FLOATS*4)

__global__ __launch_bounds__(256) void attn_core(
    const float* __restrict__ qkv, float* __restrict__ aout)
{
    extern __shared__ float sm[];
    float* s_qt = sm;                 // [32][68]  qT (scaled)
    float* s_kt = s_qt + 32*AST;      // [32][68]  kT
    float* s_v  = s_kt + 32*AST;      // [49][32]
    float* s_p  = s_v  + 49*32;       // [64][68]  scores
    float* s_pT = s_p  + 64*AST;      // [49][68]  probs (j-major)

    int widx = blockIdx.x;
    int head = blockIdx.y;
    int b  = widx >> 6;
    int wi = (widx >> 3) & 7;
    int wj = widx & 7;
    int tid  = threadIdx.x;
    int warp = tid >> 5, lane = tid & 31;
    const float scale = 0.17677669529663687f;  // 32^-0.5

    for (int idx = tid; idx < 49*8; idx += 256) {
        int n = idx >> 3, d4 = (idx & 7) << 2;
        int h  = (n/7)*8 + wi;
        int w2 = (n%7)*8 + wj;
        const float* bp = qkv + ((size_t)((b*HH + h)*WW) + w2)*576 + head*32 + d4;
        float4 qv = *(const float4*)bp;
        float4 kv = *(const float4*)(bp + 192);
        float4 vv = *(const float4*)(bp + 384);
        s_qt[(d4+0)*AST + n] = qv.x*scale;
        s_qt[(d4+1)*AST + n] = qv.y*scale;
        s_qt[(d4+2)*AST + n] = qv.z*scale;
        s_qt[(d4+3)*AST + n] = qv.w*scale;
        s_kt[(d4+0)*AST + n] = kv.x;
        s_kt[(d4+1)*AST + n] = kv.y;
        s_kt[(d4+2)*AST + n] = kv.z;
        s_kt[(d4+3)*AST + n] = kv.w;
        *(float4*)&s_v[n*32 + d4] = vv;
    }
    for (int idx = tid; idx < 32*15; idx += 256) {
        int d = idx/15, c = 49 + idx%15;
        s_qt[d*AST + c] = 0.f;
        s_kt[d*AST + c] = 0.f;
    }
    for (int idx = tid; idx < 49*15; idx += 256) {
        int j = idx/15, c = 49 + idx%15;
        s_pT[j*AST + c] = 0.f;
    }
    __syncthreads();

    {
        int tx = tid & 15, ty = tid >> 4;
        float2 acc[4][2];
#pragma unroll
        for (int i = 0; i < 4; i++) { acc[i][0] = make_float2(0,0); acc[i][1] = make_float2(0,0); }
#pragma unroll 4
        for (int d = 0; d < 32; d++) {
            float4 a4 = *(const float4*)&s_qt[d*AST + ty*4];
            float4 b4 = *(const float4*)&s_kt[d*AST + tx*4];
            float2 b01 = make_float2(b4.x, b4.y);
            float2 b23 = make_float2(b4.z, b4.w);
            float ar[4] = {a4.x, a4.y, a4.z, a4.w};
#pragma unroll
            for (int i = 0; i < 4; i++) {
                float2 a2 = make_float2(ar[i], ar[i]);
                ffma2(acc[i][0], a2, b01);
                ffma2(acc[i][1], a2, b23);
            }
        }
#pragma unroll
        for (int i = 0; i < 4; i++) {
            *(float4*)&s_p[(ty*4 + i)*AST + tx*4] =
                make_float4(acc[i][0].x, acc[i][0].y, acc[i][1].x, acc[i][1].y);
        }
    }
    __syncthreads();

    for (int i = warp; i < NTOK; i += 8) {
        const float* row = &s_p[i*AST];
        float v1 = row[lane];
        bool has2 = (lane + 32) < NTOK;
        float v2 = has2 ? row[lane + 32] : -INFINITY;
        float mx = fmaxf(v1, v2);
#pragma unroll
        for (int o = 16; o; o >>= 1) mx = fmaxf(mx, __shfl_xor_sync(0xffffffffu, mx, o));
        float e1 = expf(v1 - mx);
        float e2 = has2 ? expf(v2 - mx) : 0.f;
        float ss = e1 + e2;
#pragma unroll
        for (int o = 16; o; o >>= 1) ss += __shfl_xor_sync(0xffffffffu, ss, o);
        float inv = 1.f / ss;
        s_pT[lane*AST + i] = e1 * inv;
        if (has2) s_pT[(lane+32)*AST + i] = e2 * inv;
    }
    __syncthreads();

    {
        int ti = tid >> 3, td = tid & 7;
        float2 acc[2][2];
        acc[0][0] = make_float2(0,0); acc[0][1] = make_float2(0,0);
        acc[1][0] = make_float2(0,0); acc[1][1] = make_float2(0,0);
#pragma unroll 7
        for (int j = 0; j < NTOK; j++) {
            float2 a = *(const float2*)&s_pT[j*AST + ti*2];
            float4 b4 = *(const float4*)&s_v[j*32 + td*4];
            float2 b01 = make_float2(b4.x, b4.y);
            float2 b23 = make_float2(b4.z, b4.w);
            float2 ax = make_float2(a.x, a.x);
            float2 ay = make_float2(a.y, a.y);
            ffma2(acc[0][0], ax, b01); ffma2(acc[0][1], ax, b23);
            ffma2(acc[1][0], ay, b01); ffma2(acc[1][1], ay, b23);
        }
#pragma unroll
        for (int r = 0; r < 2; r++) {
            int i = ti*2 + r;
            if (i < NTOK) {
                int h  = (i/7)*8 + wi;
                int w2 = (i%7)*8 + wj;
                *(float4*)&aout[((size_t)((b*HH + h)*WW) + w2)*CC + head*HDIM + td*4] =
                    make_float4(to_tf32(acc[r][0].x), to_tf32(acc[r][0].y),
                                to_tf32(acc[r][1].x), to_tf32(acc[r][1].y));
            }
        }
    }
}

// ---------------------------------------------------------------------------
extern "C" void kernel_launch(void* const* d_in, const int* in_sizes, int n_in,
                              void* d_out, int out_size)
{
    int p = 0;
    const float* x = (const float*)d_in[p++];
    while (p < n_in && in_sizes[p] == 1) p++;   // skip scalar H, W if present
    const float* cpe0_w = (const float*)d_in[p++];
    const float* cpe0_b = (const float*)d_in[p++];
    const float* cpe1_w = (const float*)d_in[p++];
    const float* cpe1_b = (const float*)d_in[p++];
    const float* n1_g   = (const float*)d_in[p++];
    const float* n1_b   = (const float*)d_in[p++];
    const float* qkv_w  = (const float*)d_in[p++];
    const float* qkv_b  = (const float*)d_in[p++];
    const float* proj_w = (const float*)d_in[p++];
    const float* proj_b = (const float*)d_in[p++];
    const float* n2_g   = (const float*)d_in[p++];
    const float* n2_b   = (const float*)d_in[p++];
    const float* fc1_w  = (const float*)d_in[p++];
    const float* fc1_b  = (const float*)d_in[p++];
    const float* fc2_w  = (const float*)d_in[p++];
    const float* fc2_b  = (const float*)d_in[p++];

    float *b0, *b1, *b2, *xn, *attn, *qkv, *hbuf;
    float *wqkv, *bqkv, *wproj, *wfc1, *wfc2;
    cudaGetSymbolAddress((void**)&b0, g_buf0);
    cudaGetSymbolAddress((void**)&b1, g_buf1);
    cudaGetSymbolAddress((void**)&b2, g_buf2);
    cudaGetSymbolAddress((void**)&xn, g_xn);
    cudaGetSymbolAddress((void**)&attn, g_attn);
    cudaGetSymbolAddress((void**)&qkv, g_qkv);
    cudaGetSymbolAddress((void**)&hbuf, g_h);
    cudaGetSymbolAddress((void**)&wqkv, g_wqkv);
    cudaGetSymbolAddress((void**)&bqkv, g_bqkv);
    cudaGetSymbolAddress((void**)&wproj, g_wproj);
    cudaGetSymbolAddress((void**)&wfc1, g_wfc1);
    cudaGetSymbolAddress((void**)&wfc2, g_wfc2);

    cudaFuncSetAttribute(gemm_mma<192,false,false>,
                         cudaFuncAttributeMaxDynamicSharedMemorySize, GEMM_SMEM_BYTES);
    cudaFuncSetAttribute(gemm_mma<192,false,true>,
                         cudaFuncAttributeMaxDynamicSharedMemorySize, GEMM_SMEM_BYTES);
    cudaFuncSetAttribute(gemm_mma<192,true,false>,
                         cudaFuncAttributeMaxDynamicSharedMemorySize, GEMM_SMEM_BYTES);
    cudaFuncSetAttribute(gemm_mma<768,false,true>,
                         cudaFuncAttributeMaxDynamicSharedMemorySize, GEMM_SMEM_BYTES);
    cudaFuncSetAttribute(attn_core,
                         cudaFuncAttributeMaxDynamicSharedMemorySize, ATTN_SMEM_BYTES);

    dim3 gcpe(HH, BATCH);
    const int MB = TOKENS/128;   // 784

    permute_qkv_wt<<<(576*192)/256, 256>>>(qkv_w, qkv_b, wqkv, bqkv);
    transpose_wt<<<(192*192)/256, 256>>>(proj_w, wproj, 192, 192);
    transpose_wt<<<(768*192)/256, 256>>>(fc1_w, wfc1, 192, 768);
    transpose_wt<<<(192*768)/256, 256>>>(fc2_w, wfc2, 768, 192);

    cpe_kernel<<<gcpe, CC>>>(x, cpe0_w, cpe0_b, b0);
    ln_kernel<<<TOKENS/8, 256>>>(b0, n1_g, n1_b, xn);
    gemm_mma<192,false,false><<<dim3(MB,3), 256, GEMM_SMEM_BYTES>>>(
        xn, wqkv, bqkv, nullptr, qkv, 576);
    attn_core<<<dim3(BATCH*64, NHEAD), 256, ATTN_SMEM_BYTES>>>(qkv, attn);
    gemm_mma<192,false,true><<<dim3(MB,1), 256, GEMM_SMEM_BYTES>>>(
        attn, wproj, proj_b, b0, b1, 192);
    cpe_kernel<<<gcpe, CC>>>(b1, cpe1_w, cpe1_b, b2);
    ln_kernel<<<TOKENS/8, 256>>>(b2, n2_g, n2_b, xn);
    gemm_mma<192,true,false><<<dim3(MB,4), 256, GEMM_SMEM_BYTES>>>(
        xn, wfc1, fc1_b, nullptr, hbuf, 768);
    gemm_mma<768,false,true><<<dim3(MB,1), 256, GEMM_SMEM_BYTES>>>(
        hbuf, wfc2, fc2_b, b2, (float*)d_out, 192);
}

// round 8
// speedup vs baseline: 7.6417x; 1.3939x over previous
#include <cuda_runtime.h>
#include <cuda_bf16.h>
#include <math.h>
#include <stdint.h>

#define BATCH 32
#define HH 56
#define WW 56
#define CC 192
#define NHEAD 6
#define HDIM 32
#define NTOK 49
#define HIDDEN 768
#define TOKENS (BATCH*HH*WW)   // 100352

// Scratch (device globals — no runtime allocation allowed)
__device__ float g_buf0[TOKENS*CC];             // shortcut (after cpe0)
__device__ float g_buf1[TOKENS*CC];             // y (after attn residual)
__device__ float g_buf2[TOKENS*CC];             // y2 (after cpe1)
__device__ __nv_bfloat16 g_xn  [TOKENS*CC];     // LN output (bf16)
__device__ __nv_bfloat16 g_attn[TOKENS*CC];     // attention output (bf16)
__device__ float g_qkv [TOKENS*3*CC];           // qkv fp32 [tok][kqv][head][32]
__device__ __nv_bfloat16 g_h[TOKENS*HIDDEN];    // mlp hidden (bf16)
__device__ __nv_bfloat16 g_wqkv[576*192];       // [N][K] bf16
__device__ float        g_bqkv[576];
__device__ __nv_bfloat16 g_wproj[192*192];
__device__ __nv_bfloat16 g_wfc1[768*192];
__device__ __nv_bfloat16 g_wfc2[192*768];

__device__ __forceinline__ float gelu_exact(float x) {
    return 0.5f * x * (1.f + erff(x * 0.7071067811865475f));
}
// Packed dual-fp32 FMA (attention core)
__device__ __forceinline__ void ffma2(float2& d, float2 a, float2 b) {
    asm("fma.rn.f32x2 %0, %1, %2, %0;"
        : "+l"(reinterpret_cast<unsigned long long&>(d))
        : "l"(reinterpret_cast<unsigned long long&>(a)),
          "l"(reinterpret_cast<unsigned long long&>(b)));
}
// cp.async helpers
__device__ __forceinline__ void cp_async16(void* smem, const void* gmem) {
    unsigned s = (unsigned)__cvta_generic_to_shared(smem);
    asm volatile("cp.async.cg.shared.global [%0], [%1], 16;" :: "r"(s), "l"(gmem));
}
__device__ __forceinline__ void cp_commit() {
    asm volatile("cp.async.commit_group;");
}
template<int N> __device__ __forceinline__ void cp_wait() {
    asm volatile("cp.async.wait_group %0;" :: "n"(N));
}
// ldmatrix
__device__ __forceinline__ void ldsm_x4(uint32_t* r, uint32_t addr) {
    asm volatile("ldmatrix.sync.aligned.m8n8.x4.shared.b16 {%0,%1,%2,%3}, [%4];"
        : "=r"(r[0]), "=r"(r[1]), "=r"(r[2]), "=r"(r[3]) : "r"(addr));
}
__device__ __forceinline__ void ldsm_x2(uint32_t* r, uint32_t addr) {
    asm volatile("ldmatrix.sync.aligned.m8n8.x2.shared.b16 {%0,%1}, [%2];"
        : "=r"(r[0]), "=r"(r[1]) : "r"(addr));
}
// bf16 tensor-core mma
__device__ __forceinline__ void mma_bf16(float* c, const uint32_t* a,
                                         uint32_t b0, uint32_t b1) {
    asm volatile(
        "mma.sync.aligned.m16n8k16.row.col.f32.bf16.bf16.f32 "
        "{%0,%1,%2,%3}, {%4,%5,%6,%7}, {%8,%9}, {%0,%1,%2,%3};"
        : "+f"(c[0]), "+f"(c[1]), "+f"(c[2]), "+f"(c[3])
        : "r"(a[0]), "r"(a[1]), "r"(a[2]), "r"(a[3]), "r"(b0), "r"(b1));
}

// ---------------------------------------------------------------------------
// One-shot weight transposes (W[K][N] -> Wt[N][K], bf16)
// ---------------------------------------------------------------------------
__global__ void transpose_wt(const float* __restrict__ W, __nv_bfloat16* __restrict__ Wt,
                             int K, int N)
{
    int idx = blockIdx.x*256 + threadIdx.x;
    int n = idx / K, k = idx % K;
    Wt[idx] = __float2bfloat16(W[(size_t)k*N + n]);
}
// qkv: dst row n = kk*192 + h*32 + d  <-  src col d*18 + kk*6 + h (faithful (d k h))
__global__ void permute_qkv_wt(const float* __restrict__ W,
                               const float* __restrict__ bias,
                               __nv_bfloat16* __restrict__ Wt, float* __restrict__ bq)
{
    int idx = blockIdx.x*256 + threadIdx.x;   // 576*192
    int n = idx / 192, k = idx % 192;
    int kk = n / 192;
    int rem = n % 192;
    int h = rem / 32, d = rem % 32;
    int src = d*18 + kk*6 + h;
    Wt[idx] = __float2bfloat16(W[(size_t)k*576 + src]);
    if (k == 0) bq[n] = bias[src];
}

// ---------------------------------------------------------------------------
// Depthwise 3x3 conv (SAME) + residual
// ---------------------------------------------------------------------------
__global__ void cpe_kernel(const float* __restrict__ in,
                           const float* __restrict__ wgt,
                           const float* __restrict__ bias,
                           float* __restrict__ out)
{
    int h = blockIdx.x;
    int b = blockIdx.y;
    int c = threadIdx.x;
    float kw[9];
#pragma unroll
    for (int i = 0; i < 9; i++) kw[i] = wgt[c*9 + i];
    float bb = bias[c];
    const float* base  = in  + ((size_t)b*HH*WW)*CC + c;
    float*       obase = out + ((size_t)b*HH*WW)*CC + c;

    float colL[3], colM[3], colR[3];
#pragma unroll
    for (int dy = 0; dy < 3; dy++) {
        colL[dy] = 0.f;
        int hy = h + dy - 1;
        colM[dy] = (hy >= 0 && hy < HH) ? base[(size_t)(hy*WW)*CC] : 0.f;
    }
    for (int x = 0; x < WW; x++) {
#pragma unroll
        for (int dy = 0; dy < 3; dy++) {
            int hy = h + dy - 1;
            colR[dy] = (x+1 < WW && hy >= 0 && hy < HH)
                       ? base[(size_t)(hy*WW + x + 1)*CC] : 0.f;
        }
        float acc = bb;
#pragma unroll
        for (int dy = 0; dy < 3; dy++) {
            acc = fmaf(kw[dy*3+0], colL[dy], acc);
            acc = fmaf(kw[dy*3+1], colM[dy], acc);
            acc = fmaf(kw[dy*3+2], colR[dy], acc);
        }
        obase[(size_t)(h*WW + x)*CC] = colM[1] + acc;
#pragma unroll
        for (int dy = 0; dy < 3; dy++) { colL[dy] = colM[dy]; colM[dy] = colR[dy]; }
    }
}

// ---------------------------------------------------------------------------
// Per-token LayerNorm -> bf16 output (feeds GEMMs only)
// ---------------------------------------------------------------------------
__global__ void ln_kernel(const float* __restrict__ in,
                          const float* __restrict__ g, const float* __restrict__ b,
                          __nv_bfloat16* __restrict__ out)
{
    int tok  = blockIdx.x*8 + (threadIdx.x >> 5);
    int lane = threadIdx.x & 31;
    const float* p = in + (size_t)tok*CC;
    __nv_bfloat16* o = out + (size_t)tok*CC;
    float vals[6]; float s = 0.f;
#pragma unroll
    for (int u = 0; u < 6; u++) { vals[u] = p[lane + u*32]; s += vals[u]; }
#pragma unroll
    for (int off = 16; off; off >>= 1) s += __shfl_xor_sync(0xffffffffu, s, off);
    float m = s * (1.f/192.f);
    float vv = 0.f;
#pragma unroll
    for (int u = 0; u < 6; u++) { float d = vals[u]-m; vv += d*d; }
#pragma unroll
    for (int off = 16; off; off >>= 1) vv += __shfl_xor_sync(0xffffffffu, vv, off);
    float rs = rsqrtf(vv*(1.f/192.f) + 1e-5f);
#pragma unroll
    for (int u = 0; u < 6; u++) {
        int c = lane + u*32;
        o[c] = __float2bfloat16((vals[u]-m)*rs*g[c] + b[c]);
    }
}

// ---------------------------------------------------------------------------
// bf16 mma.sync GEMM: out[M,N] = A[M,K] @ Wt[N,K]^T + bias (modes below)
// 128x192 block, 256 threads (8 warps 2x4), warp tile 64x48, k-chunk 32.
// 3-stage cp.async pipeline; smem stride 40 bf16 (80B; ldmatrix conflict-free).
// MODE: 0 = fp32 out; 1 = gelu -> bf16 out; 2 = fp32 out + residual.
// ---------------------------------------------------------------------------
#define ASTG 10240               // 128*40*2 bytes per A stage
#define BSTG 15360               // 192*40*2 bytes per B stage
#define GEMM_SMEM_BYTES (3*(ASTG+BSTG))   // 76800

__device__ __forceinline__ void stage_bf16(
    char* sA, char* sB, const __nv_bfloat16* A, const __nv_bfloat16* Wt,
    int row0, int col0, int k0, int KTOT, int tid)
{
#pragma unroll
    for (int i = 0; i < 2; i++) {                 // A: 128 rows x 4 x 16B
        int idx = tid + i*256;
        int r = idx >> 2, q = idx & 3;
        cp_async16(sA + r*80 + q*16, A + (size_t)(row0 + r)*KTOT + k0 + q*8);
    }
#pragma unroll
    for (int i = 0; i < 3; i++) {                 // B: 192 rows x 4 x 16B
        int idx = tid + i*256;
        int n = idx >> 2, q = idx & 3;
        cp_async16(sB + n*80 + q*16, Wt + (size_t)(col0 + n)*KTOT + k0 + q*8);
    }
}

template<int KTOT, int MODE>
__global__ __launch_bounds__(256) void gemm_bf16(
    const __nv_bfloat16* __restrict__ A, const __nv_bfloat16* __restrict__ Wt,
    const float* __restrict__ bias, const float* __restrict__ res,
    void* __restrict__ outv, int N)
{
    extern __shared__ char smc[];
    const int NC = KTOT/32;
    int tid = threadIdx.x;
    int wid = tid >> 5, lane = tid & 31;
    int wm = wid >> 2, wn = wid & 3;           // warp grid 2x4
    int gid = lane >> 2, tig = lane & 3;
    int col0 = blockIdx.x * 192;               // col tiles fast -> A L2 reuse
    int row0 = blockIdx.y * 128;

    float acc[4][6][4];
#pragma unroll
    for (int mi = 0; mi < 4; mi++)
#pragma unroll
        for (int ni = 0; ni < 6; ni++)
#pragma unroll
            for (int j = 0; j < 4; j++) acc[mi][ni][j] = 0.f;

    // prefetch 3 stages
#pragma unroll
    for (int c = 0; c < 3; c++) {
        stage_bf16(smc + c*ASTG, smc + 3*ASTG + c*BSTG, A, Wt,
                   row0, col0, c*32, KTOT, tid);
        cp_commit();
    }

    // per-thread ldmatrix base offsets (within a stage)
    uint32_t sbase = (uint32_t)__cvta_generic_to_shared(smc);
    uint32_t aOff = (uint32_t)((wm*64 + (lane & 7) + ((lane >> 3) & 1)*8)*80
                               + ((lane >> 4) & 1)*16);
    int l2 = lane & 15;
    uint32_t bOff = (uint32_t)(3*ASTG + (wn*48 + (l2 & 7))*80 + ((l2 >> 3) & 1)*16);

    for (int c = 0; c < NC; c++) {
        if (c + 3 <= NC) cp_wait<2>();
        else if (c + 2 == NC) cp_wait<1>();
        else cp_wait<0>();
        __syncthreads();
        int st = c % 3;
        uint32_t aB = sbase + st*ASTG + aOff;
        uint32_t bB = sbase + st*BSTG + bOff;
#pragma unroll
        for (int ks = 0; ks < 2; ks++) {
            uint32_t av[4][4], bv[6][2];
#pragma unroll
            for (int mi = 0; mi < 4; mi++)
                ldsm_x4(av[mi], aB + mi*16*80 + ks*32);
#pragma unroll
            for (int ni = 0; ni < 6; ni++)
                ldsm_x2(bv[ni], bB + ni*8*80 + ks*32);
#pragma unroll
            for (int ni = 0; ni < 6; ni++)
#pragma unroll
                for (int mi = 0; mi < 4; mi++)
                    mma_bf16(acc[mi][ni], av[mi], bv[ni][0], bv[ni][1]);
        }
        __syncthreads();
        if (c + 3 < NC) {
            stage_bf16(smc + st*ASTG, smc + 3*ASTG + st*BSTG, A, Wt,
                       row0, col0, (c + 3)*32, KTOT, tid);
            cp_commit();
        }
    }

    // epilogue: c0,c1 -> (row, 2tig..+1); c2,c3 -> (row+8)
#pragma unroll
    for (int mi = 0; mi < 4; mi++) {
        int r0 = row0 + wm*64 + mi*16 + gid;
#pragma unroll
        for (int ni = 0; ni < 6; ni++) {
            int col = col0 + wn*48 + ni*8 + 2*tig;
            float2 bb = *(const float2*)&bias[col];
            float v0x = acc[mi][ni][0] + bb.x, v0y = acc[mi][ni][1] + bb.y;
            float v1x = acc[mi][ni][2] + bb.x, v1y = acc[mi][ni][3] + bb.y;
            size_t o0 = (size_t)r0*N + col;
            size_t o1 = (size_t)(r0 + 8)*N + col;
            if (MODE == 1) {
                __nv_bfloat16* out = (__nv_bfloat16*)outv;
                __nv_bfloat162 p0 = __floats2bfloat162_rn(gelu_exact(v0x), gelu_exact(v0y));
                __nv_bfloat162 p1 = __floats2bfloat162_rn(gelu_exact(v1x), gelu_exact(v1y));
                *(__nv_bfloat162*)&out[o0] = p0;
                *(__nv_bfloat162*)&out[o1] = p1;
            } else {
                float* out = (float*)outv;
                if (MODE == 2) {
                    float2 r0v = *(const float2*)&res[o0];
                    float2 r1v = *(const float2*)&res[o1];
                    v0x += r0v.x; v0y += r0v.y;
                    v1x += r1v.x; v1y += r1v.y;
                }
                *(float2*)&out[o0] = make_float2(v0x, v0y);
                *(float2*)&out[o1] = make_float2(v1x, v1y);
            }
        }
    }
}

// ---------------------------------------------------------------------------
// Attention core: one block per (window, head). qkv fp32; out bf16.
// ---------------------------------------------------------------------------
#define AST 68
#define ATTN_SMEM_FLOATS (2*32*AST + 49*32 + 64*AST + 49*AST)
#define ATTN_SMEM_BYTES  (ATTN_SMEM_FLOATS*4)

__global__ __launch_bounds__(256) void attn_core(
    const float* __restrict__ qkv, __nv_bfloat16* __restrict__ aout)
{
    extern __shared__ float sm[];
    float* s_qt = sm;                 // [32][68]  qT (scaled)
    float* s_kt = s_qt + 32*AST;      // [32][68]  kT
    float* s_v  = s_kt + 32*AST;      // [49][32]
    float* s_p  = s_v  + 49*32;       // [64][68]  scores
    float* s_pT = s_p  + 64*AST;      // [49][68]  probs (j-major)

    int widx = blockIdx.x;
    int head = blockIdx.y;
    int b  = widx >> 6;
    int wi = (widx >> 3) & 7;
    int wj = widx & 7;
    int tid  = threadIdx.x;
    int warp = tid >> 5, lane = tid & 31;
    const float scale = 0.17677669529663687f;  // 32^-0.5

    for (int idx = tid; idx < 49*8; idx += 256) {
        int n = idx >> 3, d4 = (idx & 7) << 2;
        int h  = (n/7)*8 + wi;
        int w2 = (n%7)*8 + wj;
        const float* bp = qkv + ((size_t)((b*HH + h)*WW) + w2)*576 + head*32 + d4;
        float4 qv = *(const float4*)bp;
        float4 kv = *(const float4*)(bp + 192);
        float4 vv = *(const float4*)(bp + 384);
        s_qt[(d4+0)*AST + n] = qv.x*scale;
        s_qt[(d4+1)*AST + n] = qv.y*scale;
        s_qt[(d4+2)*AST + n] = qv.z*scale;
        s_qt[(d4+3)*AST + n] = qv.w*scale;
        s_kt[(d4+0)*AST + n] = kv.x;
        s_kt[(d4+1)*AST + n] = kv.y;
        s_kt[(d4+2)*AST + n] = kv.z;
        s_kt[(d4+3)*AST + n] = kv.w;
        *(float4*)&s_v[n*32 + d4] = vv;
    }
    for (int idx = tid; idx < 32*15; idx += 256) {
        int d = idx/15, c = 49 + idx%15;
        s_qt[d*AST + c] = 0.f;
        s_kt[d*AST + c] = 0.f;
    }
    for (int idx = tid; idx < 49*15; idx += 256) {
        int j = idx/15, c = 49 + idx%15;
        s_pT[j*AST + c] = 0.f;
    }
    __syncthreads();

    {
        int tx = tid & 15, ty = tid >> 4;
        float2 acc[4][2];
#pragma unroll
        for (int i = 0; i < 4; i++) { acc[i][0] = make_float2(0,0); acc[i][1] = make_float2(0,0); }
#pragma unroll 4
        for (int d = 0; d < 32; d++) {
            float4 a4 = *(const float4*)&s_qt[d*AST + ty*4];
            float4 b4 = *(const float4*)&s_kt[d*AST + tx*4];
            float2 b01 = make_float2(b4.x, b4.y);
            float2 b23 = make_float2(b4.z, b4.w);
            float ar[4] = {a4.x, a4.y, a4.z, a4.w};
#pragma unroll
            for (int i = 0; i < 4; i++) {
                float2 a2 = make_float2(ar[i], ar[i]);
                ffma2(acc[i][0], a2, b01);
                ffma2(acc[i][1], a2, b23);
            }
        }
#pragma unroll
        for (int i = 0; i < 4; i++) {
            *(float4*)&s_p[(ty*4 + i)*AST + tx*4] =
                make_float4(acc[i][0].x, acc[i][0].y, acc[i][1].x, acc[i][1].y);
        }
    }
    __syncthreads();

    for (int i = warp; i < NTOK; i += 8) {
        const float* row = &s_p[i*AST];
        float v1 = row[lane];
        bool has2 = (lane + 32) < NTOK;
        float v2 = has2 ? row[lane + 32] : -INFINITY;
        float mx = fmaxf(v1, v2);
#pragma unroll
        for (int o = 16; o; o >>= 1) mx = fmaxf(mx, __shfl_xor_sync(0xffffffffu, mx, o));
        float e1 = expf(v1 - mx);
        float e2 = has2 ? expf(v2 - mx) : 0.f;
        float ss = e1 + e2;
#pragma unroll
        for (int o = 16; o; o >>= 1) ss += __shfl_xor_sync(0xffffffffu, ss, o);
        float inv = 1.f / ss;
        s_pT[lane*AST + i] = e1 * inv;
        if (has2) s_pT[(lane+32)*AST + i] = e2 * inv;
    }
    __syncthreads();

    {
        int ti = tid >> 3, td = tid & 7;
        float2 acc[2][2];
        acc[0][0] = make_float2(0,0); acc[0][1] = make_float2(0,0);
        acc[1][0] = make_float2(0,0); acc[1][1] = make_float2(0,0);
#pragma unroll 7
        for (int j = 0; j < NTOK; j++) {
            float2 a = *(const float2*)&s_pT[j*AST + ti*2];
            float4 b4 = *(const float4*)&s_v[j*32 + td*4];
            float2 b01 = make_float2(b4.x, b4.y);
            float2 b23 = make_float2(b4.z, b4.w);
            float2 ax = make_float2(a.x, a.x);
            float2 ay = make_float2(a.y, a.y);
            ffma2(acc[0][0], ax, b01); ffma2(acc[0][1], ax, b23);
            ffma2(acc[1][0], ay, b01); ffma2(acc[1][1], ay, b23);
        }
#pragma unroll
        for (int r = 0; r < 2; r++) {
            int i = ti*2 + r;
            if (i < NTOK) {
                int h  = (i/7)*8 + wi;
                int w2 = (i%7)*8 + wj;
                __nv_bfloat162 p0 = __floats2bfloat162_rn(acc[r][0].x, acc[r][0].y);
                __nv_bfloat162 p1 = __floats2bfloat162_rn(acc[r][1].x, acc[r][1].y);
                uint2 pk;
                pk.x = *(uint32_t*)&p0;
                pk.y = *(uint32_t*)&p1;
                *(uint2*)&aout[((size_t)((b*HH + h)*WW) + w2)*CC + head*HDIM + td*4] = pk;
            }
        }
    }
}

// ---------------------------------------------------------------------------
extern "C" void kernel_launch(void* const* d_in, const int* in_sizes, int n_in,
                              void* d_out, int out_size)
{
    int p = 0;
    const float* x = (const float*)d_in[p++];
    while (p < n_in && in_sizes[p] == 1) p++;   // skip scalar H, W if present
    const float* cpe0_w = (const float*)d_in[p++];
    const float* cpe0_b = (const float*)d_in[p++];
    const float* cpe1_w = (const float*)d_in[p++];
    const float* cpe1_b = (const float*)d_in[p++];
    const float* n1_g   = (const float*)d_in[p++];
    const float* n1_b   = (const float*)d_in[p++];
    const float* qkv_w  = (const float*)d_in[p++];
    const float* qkv_b  = (const float*)d_in[p++];
    const float* proj_w = (const float*)d_in[p++];
    const float* proj_b = (const float*)d_in[p++];
    const float* n2_g   = (const float*)d_in[p++];
    const float* n2_b   = (const float*)d_in[p++];
    const float* fc1_w  = (const float*)d_in[p++];
    const float* fc1_b  = (const float*)d_in[p++];
    const float* fc2_w  = (const float*)d_in[p++];
    const float* fc2_b  = (const float*)d_in[p++];

    float *b0, *b1, *b2, *qkv, *bqkv;
    __nv_bfloat16 *xn, *attn, *hbuf, *wqkv, *wproj, *wfc1, *wfc2;
    cudaGetSymbolAddress((void**)&b0, g_buf0);
    cudaGetSymbolAddress((void**)&b1, g_buf1);
    cudaGetSymbolAddress((void**)&b2, g_buf2);
    cudaGetSymbolAddress((void**)&xn, g_xn);
    cudaGetSymbolAddress((void**)&attn, g_attn);
    cudaGetSymbolAddress((void**)&qkv, g_qkv);
    cudaGetSymbolAddress((void**)&hbuf, g_h);
    cudaGetSymbolAddress((void**)&wqkv, g_wqkv);
    cudaGetSymbolAddress((void**)&bqkv, g_bqkv);
    cudaGetSymbolAddress((void**)&wproj, g_wproj);
    cudaGetSymbolAddress((void**)&wfc1, g_wfc1);
    cudaGetSymbolAddress((void**)&wfc2, g_wfc2);

    cudaFuncSetAttribute(gemm_bf16<192,0>,
                         cudaFuncAttributeMaxDynamicSharedMemorySize, GEMM_SMEM_BYTES);
    cudaFuncSetAttribute(gemm_bf16<192,1>,
                         cudaFuncAttributeMaxDynamicSharedMemorySize, GEMM_SMEM_BYTES);
    cudaFuncSetAttribute(gemm_bf16<192,2>,
                         cudaFuncAttributeMaxDynamicSharedMemorySize, GEMM_SMEM_BYTES);
    cudaFuncSetAttribute(gemm_bf16<768,2>,
                         cudaFuncAttributeMaxDynamicSharedMemorySize, GEMM_SMEM_BYTES);
    cudaFuncSetAttribute(attn_core,
                         cudaFuncAttributeMaxDynamicSharedMemorySize, ATTN_SMEM_BYTES);

    dim3 gcpe(HH, BATCH);
    const int MB = TOKENS/128;   // 784

    permute_qkv_wt<<<(576*192)/256, 256>>>(qkv_w, qkv_b, wqkv, bqkv);
    transpose_wt<<<(192*192)/256, 256>>>(proj_w, wproj, 192, 192);
    transpose_wt<<<(768*192)/256, 256>>>(fc1_w, wfc1, 192, 768);
    transpose_wt<<<(192*768)/256, 256>>>(fc2_w, wfc2, 768, 192);

    cpe_kernel<<<gcpe, CC>>>(x, cpe0_w, cpe0_b, b0);
    ln_kernel<<<TOKENS/8, 256>>>(b0, n1_g, n1_b, xn);
    gemm_bf16<192,0><<<dim3(3, MB), 256, GEMM_SMEM_BYTES>>>(
        xn, wqkv, bqkv, nullptr, qkv, 576);
    attn_core<<<dim3(BATCH*64, NHEAD), 256, ATTN_SMEM_BYTES>>>(qkv, attn);
    gemm_bf16<192,2><<<dim3(1, MB), 256, GEMM_SMEM_BYTES>>>(
        attn, wproj, proj_b, b0, b1, 192);
    cpe_kernel<<<gcpe, CC>>>(b1, cpe1_w, cpe1_b, b2);
    ln_kernel<<<TOKENS/8, 256>>>(b2, n2_g, n2_b, xn);
    gemm_bf16<192,1><<<dim3(4, MB), 256, GEMM_SMEM_BYTES>>>(
        xn, wfc1, fc1_b, nullptr, hbuf, 768);
    gemm_bf16<768,2><<<dim3(1, MB), 256, GEMM_SMEM_BYTES>>>(
        hbuf, wfc2, fc2_b, b2, (float*)d_out, 192);
}

// round 9
// speedup vs baseline: 8.2463x; 1.0791x over previous
#include <cuda_runtime.h>
#include <cuda_bf16.h>
#include <math.h>
#include <stdint.h>

#define BATCH 32
#define HH 56
#define WW 56
#define CC 192
#define NHEAD 6
#define HDIM 32
#define NTOK 49
#define HIDDEN 768
#define TOKENS (BATCH*HH*WW)   // 100352

// Scratch (device globals — no runtime allocation allowed)
__device__ float g_buf0[TOKENS*CC];             // shortcut (after cpe0)
__device__ float g_buf1[TOKENS*CC];             // y (after attn residual)
__device__ float g_buf2[TOKENS*CC];             // y2 (after cpe1)
__device__ __nv_bfloat16 g_xn  [TOKENS*CC];     // LN output (bf16)
__device__ __nv_bfloat16 g_attn[TOKENS*CC];     // attention output (bf16)
__device__ __nv_bfloat16 g_qkv [TOKENS*3*CC];   // qkv bf16 [tok][kqv][head][32]
__device__ __nv_bfloat16 g_wqkv[576*192];       // [N][K] bf16
__device__ float        g_bqkv[576];
__device__ __nv_bfloat16 g_wproj[192*192];
__device__ __nv_bfloat16 g_wfc1[768*192];
__device__ __nv_bfloat16 g_wfc2[192*768];

__device__ __forceinline__ float gelu_exact(float x) {
    return 0.5f * x * (1.f + erff(x * 0.7071067811865475f));
}
// Packed dual-fp32 FMA (attention core)
__device__ __forceinline__ void ffma2(float2& d, float2 a, float2 b) {
    asm("fma.rn.f32x2 %0, %1, %2, %0;"
        : "+l"(reinterpret_cast<unsigned long long&>(d))
        : "l"(reinterpret_cast<unsigned long long&>(a)),
          "l"(reinterpret_cast<unsigned long long&>(b)));
}
// cp.async helpers
__device__ __forceinline__ void cp_async16(void* smem, const void* gmem) {
    unsigned s = (unsigned)__cvta_generic_to_shared(smem);
    asm volatile("cp.async.cg.shared.global [%0], [%1], 16;" :: "r"(s), "l"(gmem));
}
__device__ __forceinline__ void cp_commit() {
    asm volatile("cp.async.commit_group;");
}
template<int N> __device__ __forceinline__ void cp_wait() {
    asm volatile("cp.async.wait_group %0;" :: "n"(N));
}
// ldmatrix
__device__ __forceinline__ void ldsm_x4(uint32_t* r, uint32_t addr) {
    asm volatile("ldmatrix.sync.aligned.m8n8.x4.shared.b16 {%0,%1,%2,%3}, [%4];"
        : "=r"(r[0]), "=r"(r[1]), "=r"(r[2]), "=r"(r[3]) : "r"(addr));
}
__device__ __forceinline__ void ldsm_x2(uint32_t* r, uint32_t addr) {
    asm volatile("ldmatrix.sync.aligned.m8n8.x2.shared.b16 {%0,%1}, [%2];"
        : "=r"(r[0]), "=r"(r[1]) : "r"(addr));
}
// bf16 tensor-core mma
__device__ __forceinline__ void mma_bf16(float* c, const uint32_t* a,
                                         uint32_t b0, uint32_t b1) {
    asm volatile(
        "mma.sync.aligned.m16n8k16.row.col.f32.bf16.bf16.f32 "
        "{%0,%1,%2,%3}, {%4,%5,%6,%7}, {%8,%9}, {%0,%1,%2,%3};"
        : "+f"(c[0]), "+f"(c[1]), "+f"(c[2]), "+f"(c[3])
        : "r"(a[0]), "r"(a[1]), "r"(a[2]), "r"(a[3]), "r"(b0), "r"(b1));
}

// ---------------------------------------------------------------------------
// One-shot weight prep (4 jobs merged): W[K][N] -> Wt[N][K], bf16.
// Job 0 also applies the faithful (d k h) qkv column permutation.
// ---------------------------------------------------------------------------
__global__ void prep_weights(
    const float* __restrict__ qkv_w, const float* __restrict__ qkv_b,
    const float* __restrict__ proj_w, const float* __restrict__ fc1_w,
    const float* __restrict__ fc2_w,
    __nv_bfloat16* __restrict__ wqkv, float* __restrict__ bqkv,
    __nv_bfloat16* __restrict__ wproj, __nv_bfloat16* __restrict__ wfc1,
    __nv_bfloat16* __restrict__ wfc2)
{
    int job = blockIdx.y;
    int idx = blockIdx.x*256 + threadIdx.x;
    if (job == 0) {
        if (idx >= 576*192) return;
        int n = idx / 192, k = idx % 192;
        int kk = n / 192;
        int rem = n % 192;
        int h = rem / 32, d = rem % 32;
        int src = d*18 + kk*6 + h;
        wqkv[idx] = __float2bfloat16(qkv_w[(size_t)k*576 + src]);
        if (k == 0) bqkv[n] = qkv_b[src];
    } else if (job == 1) {
        if (idx >= 192*192) return;
        int n = idx / 192, k = idx % 192;
        wproj[idx] = __float2bfloat16(proj_w[(size_t)k*192 + n]);
    } else if (job == 2) {
        if (idx >= 768*192) return;
        int n = idx / 192, k = idx % 192;
        wfc1[idx] = __float2bfloat16(fc1_w[(size_t)k*768 + n]);
    } else {
        if (idx >= 192*768) return;
        int n = idx / 768, k = idx % 768;
        wfc2[idx] = __float2bfloat16(fc2_w[(size_t)k*192 + n]);
    }
}

// ---------------------------------------------------------------------------
// Depthwise 3x3 conv (SAME) + residual
// ---------------------------------------------------------------------------
__global__ void cpe_kernel(const float* __restrict__ in,
                           const float* __restrict__ wgt,
                           const float* __restrict__ bias,
                           float* __restrict__ out)
{
    int h = blockIdx.x;
    int b = blockIdx.y;
    int c = threadIdx.x;
    float kw[9];
#pragma unroll
    for (int i = 0; i < 9; i++) kw[i] = wgt[c*9 + i];
    float bb = bias[c];
    const float* base  = in  + ((size_t)b*HH*WW)*CC + c;
    float*       obase = out + ((size_t)b*HH*WW)*CC + c;

    float colL[3], colM[3], colR[3];
#pragma unroll
    for (int dy = 0; dy < 3; dy++) {
        colL[dy] = 0.f;
        int hy = h + dy - 1;
        colM[dy] = (hy >= 0 && hy < HH) ? base[(size_t)(hy*WW)*CC] : 0.f;
    }
    for (int x = 0; x < WW; x++) {
#pragma unroll
        for (int dy = 0; dy < 3; dy++) {
            int hy = h + dy - 1;
            colR[dy] = (x+1 < WW && hy >= 0 && hy < HH)
                       ? base[(size_t)(hy*WW + x + 1)*CC] : 0.f;
        }
        float acc = bb;
#pragma unroll
        for (int dy = 0; dy < 3; dy++) {
            acc = fmaf(kw[dy*3+0], colL[dy], acc);
            acc = fmaf(kw[dy*3+1], colM[dy], acc);
            acc = fmaf(kw[dy*3+2], colR[dy], acc);
        }
        obase[(size_t)(h*WW + x)*CC] = colM[1] + acc;
#pragma unroll
        for (int dy = 0; dy < 3; dy++) { colL[dy] = colM[dy]; colM[dy] = colR[dy]; }
    }
}

// ---------------------------------------------------------------------------
// Per-token LayerNorm -> bf16 output (feeds GEMMs only)
// ---------------------------------------------------------------------------
__global__ void ln_kernel(const float* __restrict__ in,
                          const float* __restrict__ g, const float* __restrict__ b,
                          __nv_bfloat16* __restrict__ out)
{
    int tok  = blockIdx.x*8 + (threadIdx.x >> 5);
    int lane = threadIdx.x & 31;
    const float* p = in + (size_t)tok*CC;
    __nv_bfloat16* o = out + (size_t)tok*CC;
    float vals[6]; float s = 0.f;
#pragma unroll
    for (int u = 0; u < 6; u++) { vals[u] = p[lane + u*32]; s += vals[u]; }
#pragma unroll
    for (int off = 16; off; off >>= 1) s += __shfl_xor_sync(0xffffffffu, s, off);
    float m = s * (1.f/192.f);
    float vv = 0.f;
#pragma unroll
    for (int u = 0; u < 6; u++) { float d = vals[u]-m; vv += d*d; }
#pragma unroll
    for (int off = 16; off; off >>= 1) vv += __shfl_xor_sync(0xffffffffu, vv, off);
    float rs = rsqrtf(vv*(1.f/192.f) + 1e-5f);
#pragma unroll
    for (int u = 0; u < 6; u++) {
        int c = lane + u*32;
        o[c] = __float2bfloat16((vals[u]-m)*rs*g[c] + b[c]);
    }
}

// ---------------------------------------------------------------------------
// bf16 mma.sync GEMM: out[M,N] = A[M,K] @ Wt[N,K]^T + bias
// MODE: 2 = fp32 out + residual; 3 = bf16 out.
// ---------------------------------------------------------------------------
#define ASTG 10240               // 128*40*2 bytes per A stage
#define BSTG 15360               // 192*40*2 bytes per B stage
#define GEMM_SMEM_BYTES (3*(ASTG+BSTG))   // 76800

__device__ __forceinline__ void stage_bf16(
    char* sA, char* sB, const __nv_bfloat16* A, const __nv_bfloat16* Wt,
    int row0, int col0, int k0, int KTOT, int tid)
{
#pragma unroll
    for (int i = 0; i < 2; i++) {                 // A: 128 rows x 4 x 16B
        int idx = tid + i*256;
        int r = idx >> 2, q = idx & 3;
        cp_async16(sA + r*80 + q*16, A + (size_t)(row0 + r)*KTOT + k0 + q*8);
    }
#pragma unroll
    for (int i = 0; i < 3; i++) {                 // B: 192 rows x 4 x 16B
        int idx = tid + i*256;
        int n = idx >> 2, q = idx & 3;
        cp_async16(sB + n*80 + q*16, Wt + (size_t)(col0 + n)*KTOT + k0 + q*8);
    }
}

template<int KTOT, int MODE>
__global__ __launch_bounds__(256) void gemm_bf16(
    const __nv_bfloat16* __restrict__ A, const __nv_bfloat16* __restrict__ Wt,
    const float* __restrict__ bias, const float* __restrict__ res,
    void* __restrict__ outv, int N)
{
    extern __shared__ char smc[];
    const int NC = KTOT/32;
    int tid = threadIdx.x;
    int wid = tid >> 5, lane = tid & 31;
    int wm = wid >> 2, wn = wid & 3;           // warp grid 2x4
    int gid = lane >> 2, tig = lane & 3;
    int col0 = blockIdx.x * 192;               // col tiles fast -> A L2 reuse
    int row0 = blockIdx.y * 128;

    float acc[4][6][4];
#pragma unroll
    for (int mi = 0; mi < 4; mi++)
#pragma unroll
        for (int ni = 0; ni < 6; ni++)
#pragma unroll
            for (int j = 0; j < 4; j++) acc[mi][ni][j] = 0.f;

#pragma unroll
    for (int c = 0; c < 3; c++) {
        stage_bf16(smc + c*ASTG, smc + 3*ASTG + c*BSTG, A, Wt,
                   row0, col0, c*32, KTOT, tid);
        cp_commit();
    }

    uint32_t sbase = (uint32_t)__cvta_generic_to_shared(smc);
    uint32_t aOff = (uint32_t)((wm*64 + (lane & 7) + ((lane >> 3) & 1)*8)*80
                               + ((lane >> 4) & 1)*16);
    int l2 = lane & 15;
    uint32_t bOff = (uint32_t)(3*ASTG + (wn*48 + (l2 & 7))*80 + ((l2 >> 3) & 1)*16);

    for (int c = 0; c < NC; c++) {
        if (c + 3 <= NC) cp_wait<2>();
        else if (c + 2 == NC) cp_wait<1>();
        else cp_wait<0>();
        __syncthreads();
        int st = c % 3;
        uint32_t aB = sbase + st*ASTG + aOff;
        uint32_t bB = sbase + st*BSTG + bOff;
#pragma unroll
        for (int ks = 0; ks < 2; ks++) {
            uint32_t av[4][4], bv[6][2];
#pragma unroll
            for (int mi = 0; mi < 4; mi++)
                ldsm_x4(av[mi], aB + mi*16*80 + ks*32);
#pragma unroll
            for (int ni = 0; ni < 6; ni++)
                ldsm_x2(bv[ni], bB + ni*8*80 + ks*32);
#pragma unroll
            for (int ni = 0; ni < 6; ni++)
#pragma unroll
                for (int mi = 0; mi < 4; mi++)
                    mma_bf16(acc[mi][ni], av[mi], bv[ni][0], bv[ni][1]);
        }
        __syncthreads();
        if (c + 3 < NC) {
            stage_bf16(smc + st*ASTG, smc + 3*ASTG + st*BSTG, A, Wt,
                       row0, col0, (c + 3)*32, KTOT, tid);
            cp_commit();
        }
    }

#pragma unroll
    for (int mi = 0; mi < 4; mi++) {
        int r0 = row0 + wm*64 + mi*16 + gid;
#pragma unroll
        for (int ni = 0; ni < 6; ni++) {
            int col = col0 + wn*48 + ni*8 + 2*tig;
            float2 bb = *(const float2*)&bias[col];
            float v0x = acc[mi][ni][0] + bb.x, v0y = acc[mi][ni][1] + bb.y;
            float v1x = acc[mi][ni][2] + bb.x, v1y = acc[mi][ni][3] + bb.y;
            size_t o0 = (size_t)r0*N + col;
            size_t o1 = (size_t)(r0 + 8)*N + col;
            if (MODE == 3) {
                __nv_bfloat16* out = (__nv_bfloat16*)outv;
                __nv_bfloat162 p0 = __floats2bfloat162_rn(v0x, v0y);
                __nv_bfloat162 p1 = __floats2bfloat162_rn(v1x, v1y);
                *(__nv_bfloat162*)&out[o0] = p0;
                *(__nv_bfloat162*)&out[o1] = p1;
            } else {
                float* out = (float*)outv;
                float2 r0v = *(const float2*)&res[o0];
                float2 r1v = *(const float2*)&res[o1];
                v0x += r0v.x; v0y += r0v.y;
                v1x += r1v.x; v1y += r1v.y;
                *(float2*)&out[o0] = make_float2(v0x, v0y);
                *(float2*)&out[o1] = make_float2(v1x, v1y);
            }
        }
    }
}

// ---------------------------------------------------------------------------
// Fused MLP: out = res + fc2b + gelu(xn@fc1 + fc1b) @ fc2
// 128-token block; X resident in smem; 12 hidden tiles of 64; fc2 acc in regs.
// ---------------------------------------------------------------------------
#define MSX  0                          // 128*400 = 51200  (X: stride 200 bf16)
#define MSB1 51200                      // 2 x 64*400 = 51200
#define MSH  (51200+51200)              // 128*144 = 18432  (h: stride 72 bf16)
#define MSB2 (51200+51200+18432)        // 2 x 192*144 = 55296
#define MLP_SMEM 176128

__device__ __forceinline__ void mlp_stage_b(
    char* smc, const __nv_bfloat16* wfc1, const __nv_bfloat16* wfc2,
    int t, int tid)
{
    char* b1 = smc + MSB1 + (t & 1)*25600;
    char* b2 = smc + MSB2 + (t & 1)*27648;
#pragma unroll
    for (int i = 0; i < 6; i++) {                 // B1: 64 rows x 24 chunks
        int idx = tid + i*256;
        int n = idx / 24, q = idx % 24;
        cp_async16(b1 + n*400 + q*16, wfc1 + (size_t)(t*64 + n)*192 + q*8);
    }
#pragma unroll
    for (int i = 0; i < 6; i++) {                 // B2: 192 rows x 8 chunks
        int idx = tid + i*256;
        int n = idx >> 3, q = idx & 7;
        cp_async16(b2 + n*144 + q*16, wfc2 + (size_t)n*768 + t*64 + q*8);
    }
}

__global__ __launch_bounds__(256) void mlp_fused(
    const __nv_bfloat16* __restrict__ xn,
    const __nv_bfloat16* __restrict__ wfc1, const float* __restrict__ fc1b,
    const __nv_bfloat16* __restrict__ wfc2, const float* __restrict__ fc2b,
    const float* __restrict__ res, float* __restrict__ out)
{
    extern __shared__ char smc[];
    int tid = threadIdx.x;
    int wid = tid >> 5, lane = tid & 31;
    int wm = wid >> 2, wn = wid & 3;
    int gid = lane >> 2, tig = lane & 3;
    int l2 = lane & 15;
    int row0 = blockIdx.x * 128;

    float acc2[4][6][4];
#pragma unroll
    for (int mi = 0; mi < 4; mi++)
#pragma unroll
        for (int ni = 0; ni < 6; ni++)
#pragma unroll
            for (int j = 0; j < 4; j++) acc2[mi][ni][j] = 0.f;

    // prologue: X + tiles 0,1
#pragma unroll
    for (int i = 0; i < 12; i++) {               // X: 128 rows x 24 chunks
        int idx = tid + i*256;
        int r = idx / 24, q = idx % 24;
        cp_async16(smc + MSX + r*400 + q*16, xn + (size_t)(row0 + r)*192 + q*8);
    }
    mlp_stage_b(smc, wfc1, wfc2, 0, tid);
    cp_commit();
    mlp_stage_b(smc, wfc1, wfc2, 1, tid);
    cp_commit();

    uint32_t sbase = (uint32_t)__cvta_generic_to_shared(smc);
    uint32_t aX  = sbase + MSX + (wm*64 + (lane & 7) + ((lane >> 3) & 1)*8)*400
                   + ((lane >> 4) & 1)*16;
    uint32_t aH  = sbase + MSH + (wm*64 + (lane & 7) + ((lane >> 3) & 1)*8)*144
                   + ((lane >> 4) & 1)*16;

    for (int t = 0; t < 12; t++) {
        if (t < 11) cp_wait<1>(); else cp_wait<0>();
        __syncthreads();
        int buf = t & 1;

        // ---- fc1: 128x64 tile, K=192 ----
        uint32_t bB1 = sbase + MSB1 + buf*25600
                     + (wn*16 + (l2 & 7))*400 + ((l2 >> 3) & 1)*16;
        float acc1[4][2][4];
#pragma unroll
        for (int mi = 0; mi < 4; mi++)
#pragma unroll
            for (int nj = 0; nj < 2; nj++)
#pragma unroll
                for (int j = 0; j < 4; j++) acc1[mi][nj][j] = 0.f;
#pragma unroll
        for (int ks = 0; ks < 12; ks++) {
            uint32_t av[4][4], bv[2][2];
#pragma unroll
            for (int mi = 0; mi < 4; mi++)
                ldsm_x4(av[mi], aX + mi*16*400 + ks*32);
#pragma unroll
            for (int nj = 0; nj < 2; nj++)
                ldsm_x2(bv[nj], bB1 + nj*8*400 + ks*32);
#pragma unroll
            for (int nj = 0; nj < 2; nj++)
#pragma unroll
                for (int mi = 0; mi < 4; mi++)
                    mma_bf16(acc1[mi][nj], av[mi], bv[nj][0], bv[nj][1]);
        }
        // gelu -> sH (bf16, stride 72)
#pragma unroll
        for (int mi = 0; mi < 4; mi++) {
            int r0 = wm*64 + mi*16 + gid;
#pragma unroll
            for (int nj = 0; nj < 2; nj++) {
                int colh = wn*16 + nj*8 + 2*tig;
                float2 bb = *(const float2*)&fc1b[t*64 + colh];
                __nv_bfloat162 p0 = __floats2bfloat162_rn(
                    gelu_exact(acc1[mi][nj][0] + bb.x),
                    gelu_exact(acc1[mi][nj][1] + bb.y));
                __nv_bfloat162 p1 = __floats2bfloat162_rn(
                    gelu_exact(acc1[mi][nj][2] + bb.x),
                    gelu_exact(acc1[mi][nj][3] + bb.y));
                *(__nv_bfloat162*)(smc + MSH + r0*144 + colh*2) = p0;
                *(__nv_bfloat162*)(smc + MSH + (r0+8)*144 + colh*2) = p1;
            }
        }
        __syncthreads();

        // ---- fc2: acc2 += h(128x64) @ wfc2_tile, K=64 ----
        uint32_t bB2 = sbase + MSB2 + buf*27648
                     + (wn*48 + (l2 & 7))*144 + ((l2 >> 3) & 1)*16;
#pragma unroll
        for (int ks = 0; ks < 4; ks++) {
            uint32_t av[4][4], bv[6][2];
#pragma unroll
            for (int mi = 0; mi < 4; mi++)
                ldsm_x4(av[mi], aH + mi*16*144 + ks*32);
#pragma unroll
            for (int ni = 0; ni < 6; ni++)
                ldsm_x2(bv[ni], bB2 + ni*8*144 + ks*32);
#pragma unroll
            for (int ni = 0; ni < 6; ni++)
#pragma unroll
                for (int mi = 0; mi < 4; mi++)
                    mma_bf16(acc2[mi][ni], av[mi], bv[ni][0], bv[ni][1]);
        }
        __syncthreads();
        if (t + 2 < 12) {
            mlp_stage_b(smc, wfc1, wfc2, t + 2, tid);
            cp_commit();
        }
    }

    // epilogue: residual + bias, fp32 out (N=192)
#pragma unroll
    for (int mi = 0; mi < 4; mi++) {
        int r0 = row0 + wm*64 + mi*16 + gid;
#pragma unroll
        for (int ni = 0; ni < 6; ni++) {
            int col = wn*48 + ni*8 + 2*tig;
            float2 bb = *(const float2*)&fc2b[col];
            size_t o0 = (size_t)r0*192 + col;
            size_t o1 = (size_t)(r0 + 8)*192 + col;
            float2 r0v = *(const float2*)&res[o0];
            float2 r1v = *(const float2*)&res[o1];
            *(float2*)&out[o0] = make_float2(acc2[mi][ni][0] + bb.x + r0v.x,
                                             acc2[mi][ni][1] + bb.y + r0v.y);
            *(float2*)&out[o1] = make_float2(acc2[mi][ni][2] + bb.x + r1v.x,
                                             acc2[mi][ni][3] + bb.y + r1v.y);
        }
    }
}

// ---------------------------------------------------------------------------
// Attention core: one block per (window, head). qkv bf16; out bf16.
// ---------------------------------------------------------------------------
#define AST 68
#define ATTN_SMEM_FLOATS (2*32*AST + 49*32 + 64*AST + 49*AST)
#define ATTN_SMEM_BYTES  (ATTN_SMEM_FLOATS*4)

__global__ __launch_bounds__(256) void attn_core(
    const __nv_bfloat16* __restrict__ qkv, __nv_bfloat16* __restrict__ aout)
{
    extern __shared__ float sm[];
    float* s_qt = sm;                 // [32][68]  qT (scaled)
    float* s_kt = s_qt + 32*AST;      // [32][68]  kT
    float* s_v  = s_kt + 32*AST;      // [49][32]
    float* s_p  = s_v  + 49*32;       // [64][68]  scores
    float* s_pT = s_p  + 64*AST;      // [49][68]  probs (j-major)

    int widx = blockIdx.x;
    int head = blockIdx.y;
    int b  = widx >> 6;
    int wi = (widx >> 3) & 7;
    int wj = widx & 7;
    int tid  = threadIdx.x;
    int warp = tid >> 5, lane = tid & 31;
    const float scale = 0.17677669529663687f;  // 32^-0.5

    for (int idx = tid; idx < 49*4; idx += 256) {
        int n = idx >> 2, d8 = (idx & 3) << 3;
        int h  = (n/7)*8 + wi;
        int w2 = (n%7)*8 + wj;
        const __nv_bfloat16* bp =
            qkv + ((size_t)((b*HH + h)*WW) + w2)*576 + head*32 + d8;
        uint4 qv = *(const uint4*)bp;
        uint4 kv = *(const uint4*)(bp + 192);
        uint4 vv = *(const uint4*)(bp + 384);
        const __nv_bfloat162* qp = (const __nv_bfloat162*)&qv;
        const __nv_bfloat162* kp = (const __nv_bfloat162*)&kv;
        const __nv_bfloat162* vp = (const __nv_bfloat162*)&vv;
#pragma unroll
        for (int j = 0; j < 4; j++) {
            float2 qf = __bfloat1622float2(qp[j]);
            float2 kf = __bfloat1622float2(kp[j]);
            float2 vf = __bfloat1622float2(vp[j]);
            s_qt[(d8 + 2*j + 0)*AST + n] = qf.x*scale;
            s_qt[(d8 + 2*j + 1)*AST + n] = qf.y*scale;
            s_kt[(d8 + 2*j + 0)*AST + n] = kf.x;
            s_kt[(d8 + 2*j + 1)*AST + n] = kf.y;
            s_v[n*32 + d8 + 2*j + 0] = vf.x;
            s_v[n*32 + d8 + 2*j + 1] = vf.y;
        }
    }
    for (int idx = tid; idx < 32*15; idx += 256) {
        int d = idx/15, c = 49 + idx%15;
        s_qt[d*AST + c] = 0.f;
        s_kt[d*AST + c] = 0.f;
    }
    for (int idx = tid; idx < 49*15; idx += 256) {
        int j = idx/15, c = 49 + idx%15;
        s_pT[j*AST + c] = 0.f;
    }
    __syncthreads();

    {
        int tx = tid & 15, ty = tid >> 4;
        float2 acc[4][2];
#pragma unroll
        for (int i = 0; i < 4; i++) { acc[i][0] = make_float2(0,0); acc[i][1] = make_float2(0,0); }
#pragma unroll 4
        for (int d = 0; d < 32; d++) {
            float4 a4 = *(const float4*)&s_qt[d*AST + ty*4];
            float4 b4 = *(const float4*)&s_kt[d*AST + tx*4];
            float2 b01 = make_float2(b4.x, b4.y);
            float2 b23 = make_float2(b4.z, b4.w);
            float ar[4] = {a4.x, a4.y, a4.z, a4.w};
#pragma unroll
            for (int i = 0; i < 4; i++) {
                float2 a2 = make_float2(ar[i], ar[i]);
                ffma2(acc[i][0], a2, b01);
                ffma2(acc[i][1], a2, b23);
            }
        }
#pragma unroll
        for (int i = 0; i < 4; i++) {
            *(float4*)&s_p[(ty*4 + i)*AST + tx*4] =
                make_float4(acc[i][0].x, acc[i][0].y, acc[i][1].x, acc[i][1].y);
        }
    }
    __syncthreads();

    for (int i = warp; i < NTOK; i += 8) {
        const float* row = &s_p[i*AST];
        float v1 = row[lane];
        bool has2 = (lane + 32) < NTOK;
        float v2 = has2 ? row[lane + 32] : -INFINITY;
        float mx = fmaxf(v1, v2);
#pragma unroll
        for (int o = 16; o; o >>= 1) mx = fmaxf(mx, __shfl_xor_sync(0xffffffffu, mx, o));
        float e1 = expf(v1 - mx);
        float e2 = has2 ? expf(v2 - mx) : 0.f;
        float ss = e1 + e2;
#pragma unroll
        for (int o = 16; o; o >>= 1) ss += __shfl_xor_sync(0xffffffffu, ss, o);
        float inv = 1.f / ss;
        s_pT[lane*AST + i] = e1 * inv;
        if (has2) s_pT[(lane+32)*AST + i] = e2 * inv;
    }
    __syncthreads();

    {
        int ti = tid >> 3, td = tid & 7;
        float2 acc[2][2];
        acc[0][0] = make_float2(0,0); acc[0][1] = make_float2(0,0);
        acc[1][0] = make_float2(0,0); acc[1][1] = make_float2(0,0);
#pragma unroll 7
        for (int j = 0; j < NTOK; j++) {
            float2 a = *(const float2*)&s_pT[j*AST + ti*2];
            float4 b4 = *(const float4*)&s_v[j*32 + td*4];
            float2 b01 = make_float2(b4.x, b4.y);
            float2 b23 = make_float2(b4.z, b4.w);
            float2 ax = make_float2(a.x, a.x);
            float2 ay = make_float2(a.y, a.y);
            ffma2(acc[0][0], ax, b01); ffma2(acc[0][1], ax, b23);
            ffma2(acc[1][0], ay, b01); ffma2(acc[1][1], ay, b23);
        }
#pragma unroll
        for (int r = 0; r < 2; r++) {
            int i = ti*2 + r;
            if (i < NTOK) {
                int h  = (i/7)*8 + wi;
                int w2 = (i%7)*8 + wj;
                __nv_bfloat162 p0 = __floats2bfloat162_rn(acc[r][0].x, acc[r][0].y);
                __nv_bfloat162 p1 = __floats2bfloat162_rn(acc[r][1].x, acc[r][1].y);
                uint2 pk;
                pk.x = *(uint32_t*)&p0;
                pk.y = *(uint32_t*)&p1;
                *(uint2*)&aout[((size_t)((b*HH + h)*WW) + w2)*CC + head*HDIM + td*4] = pk;
            }
        }
    }
}

// ---------------------------------------------------------------------------
extern "C" void kernel_launch(void* const* d_in, const int* in_sizes, int n_in,
                              void* d_out, int out_size)
{
    int p = 0;
    const float* x = (const float*)d_in[p++];
    while (p < n_in && in_sizes[p] == 1) p++;   // skip scalar H, W if present
    const float* cpe0_w = (const float*)d_in[p++];
    const float* cpe0_b = (const float*)d_in[p++];
    const float* cpe1_w = (const float*)d_in[p++];
    const float* cpe1_b = (const float*)d_in[p++];
    const float* n1_g   = (const float*)d_in[p++];
    const float* n1_b   = (const float*)d_in[p++];
    const float* qkv_w  = (const float*)d_in[p++];
    const float* qkv_b  = (const float*)d_in[p++];
    const float* proj_w = (const float*)d_in[p++];
    const float* proj_b = (const float*)d_in[p++];
    const float* n2_g   = (const float*)d_in[p++];
    const float* n2_b   = (const float*)d_in[p++];
    const float* fc1_w  = (const float*)d_in[p++];
    const float* fc1_b  = (const float*)d_in[p++];
    const float* fc2_w  = (const float*)d_in[p++];
    const float* fc2_b  = (const float*)d_in[p++];

    float *b0, *b1, *b2, *bqkv;
    __nv_bfloat16 *xn, *attn, *qkv, *wqkv, *wproj, *wfc1, *wfc2;
    cudaGetSymbolAddress((void**)&b0, g_buf0);
    cudaGetSymbolAddress((void**)&b1, g_buf1);
    cudaGetSymbolAddress((void**)&b2, g_buf2);
    cudaGetSymbolAddress((void**)&xn, g_xn);
    cudaGetSymbolAddress((void**)&attn, g_attn);
    cudaGetSymbolAddress((void**)&qkv, g_qkv);
    cudaGetSymbolAddress((void**)&wqkv, g_wqkv);
    cudaGetSymbolAddress((void**)&bqkv, g_bqkv);
    cudaGetSymbolAddress((void**)&wproj, g_wproj);
    cudaGetSymbolAddress((void**)&wfc1, g_wfc1);
    cudaGetSymbolAddress((void**)&wfc2, g_wfc2);

    cudaFuncSetAttribute(gemm_bf16<192,3>,
                         cudaFuncAttributeMaxDynamicSharedMemorySize, GEMM_SMEM_BYTES);
    cudaFuncSetAttribute(gemm_bf16<192,2>,
                         cudaFuncAttributeMaxDynamicSharedMemorySize, GEMM_SMEM_BYTES);
    cudaFuncSetAttribute(mlp_fused,
                         cudaFuncAttributeMaxDynamicSharedMemorySize, MLP_SMEM);
    cudaFuncSetAttribute(attn_core,
                         cudaFuncAttributeMaxDynamicSharedMemorySize, ATTN_SMEM_BYTES);

    dim3 gcpe(HH, BATCH);
    const int MB = TOKENS/128;   // 784

    prep_weights<<<dim3(576, 4), 256>>>(qkv_w, qkv_b, proj_w, fc1_w, fc2_w,
                                        wqkv, bqkv, wproj, wfc1, wfc2);
    cpe_kernel<<<gcpe, CC>>>(x, cpe0_w, cpe0_b, b0);
    ln_kernel<<<TOKENS/8, 256>>>(b0, n1_g, n1_b, xn);
    gemm_bf16<192,3><<<dim3(3, MB), 256, GEMM_SMEM_BYTES>>>(
        xn, wqkv, bqkv, nullptr, qkv, 576);
    attn_core<<<dim3(BATCH*64, NHEAD), 256, ATTN_SMEM_BYTES>>>(qkv, attn);
    gemm_bf16<192,2><<<dim3(1, MB), 256, GEMM_SMEM_BYTES>>>(
        attn, wproj, proj_b, b0, b1, 192);
    cpe_kernel<<<gcpe, CC>>>(b1, cpe1_w, cpe1_b, b2);
    ln_kernel<<<TOKENS/8, 256>>>(b2, n2_g, n2_b, xn);
    mlp_fused<<<MB, 256, MLP_SMEM>>>(xn, wfc1, fc1_b, wfc2, fc2_b,
                                     b2, (float*)d_out);
}